// round 12
// baseline (speedup 1.0000x reference)
#include <cuda_runtime.h>
#include <math.h>

// ---------------- problem constants ----------------
#define TT 2048
#define BB 8
#define DD 128
#define HH 4
#define NTOK (BB*TT)          // 16384
#define SCALE 0.17677669529663687f   // 1/sqrt(32)
#define LAMBDA_INIT 0.8f
#define LN_EPS 1e-5f

// banded attention config
#define W_MAX 80
#define QT 128
#define QW 8
#define NW 16
#define KROWS (QT + 2*W_MAX + 1)   // 289 (cap case)
#define KLD 68

typedef unsigned long long u64;
typedef unsigned int u32;

// ---------------- scratch ----------------
__device__ float g_mu[NTOK];
__device__ float g_rs[NTOK];
__device__ float g_y [NTOK*768];
__device__ float g_ho[NTOK*256];

// ---------------- helpers ----------------
__device__ __forceinline__ u64 pk2(float x, float y) {
    u64 r; asm("mov.b64 %0, {%1, %2};" : "=l"(r) : "f"(x), "f"(y)); return r;
}
__device__ __forceinline__ void up2(u64 v, float& x, float& y) {
    asm("mov.b64 {%0, %1}, %2;" : "=f"(x), "=f"(y) : "l"(v));
}
__device__ __forceinline__ u64 f2fma(u64 a, u64 b, u64 c) {
    u64 d; asm("fma.rn.f32x2 %0, %1, %2, %3;" : "=l"(d) : "l"(a), "l"(b), "l"(c));
    return d;
}
__device__ __forceinline__ float warpsum(float v) {
    #pragma unroll
    for (int o = 16; o; o >>= 1) v += __shfl_xor_sync(0xffffffffu, v, o);
    return v;
}
__device__ __forceinline__ u32 bfpack(float upper, float lower) {
    u32 r; asm("cvt.rn.bf16x2.f32 %0, %1, %2;" : "=r"(r) : "f"(upper), "f"(lower));
    return r;
}
__device__ __forceinline__ void bfsplit(float x0, float x1, u32& h, u32& l) {
    h = bfpack(x1, x0);
    float f0 = __uint_as_float(h << 16);
    float f1 = __uint_as_float(h & 0xFFFF0000u);
    l = bfpack(x1 - f1, x0 - f0);
}
__device__ __forceinline__ void mma_bf16(float* c, u32 a0, u32 a1, u32 a2, u32 a3,
                                         u32 b0, u32 b1) {
    asm volatile(
        "mma.sync.aligned.m16n8k16.row.col.f32.bf16.bf16.f32 "
        "{%0,%1,%2,%3}, {%4,%5,%6,%7}, {%8,%9}, {%0,%1,%2,%3};"
        : "+f"(c[0]), "+f"(c[1]), "+f"(c[2]), "+f"(c[3])
        : "r"(a0), "r"(a1), "r"(a2), "r"(a3), "r"(b0), "r"(b1));
}

// ---------------- stage 1: layernorm stats only ----------------
__global__ void ln_stats(const float* __restrict__ tok) {
    int t = blockIdx.x * 8 + (threadIdx.x >> 5);
    int lane = threadIdx.x & 31;
    const float4* src = (const float4*)(tok + (size_t)t * DD);
    float4 x = src[lane];
    float s  = x.x + x.y + x.z + x.w;
    float sq = x.x*x.x + x.y*x.y + x.z*x.z + x.w*x.w;
    s  = warpsum(s);
    sq = warpsum(sq);
    float mu  = s * (1.0f/128.0f);
    float var = sq * (1.0f/128.0f) - mu*mu;
    if (lane == 0) {
        g_mu[t] = mu;
        g_rs[t] = rsqrtf(var + LN_EPS);
    }
}

// ---------------- 3xBF16 TC GEMM, MT=64 tile, 2-stage double buffer ----------------
// Per stage: A u32[64][20] hi+lo, B u32[16][136] hi+lo.  STAGE_U32 = 6912.
template<int KTOT, int LDA_G, int LDB_G, bool RESID, bool LNA>
__device__ __forceinline__ void gemm_tc_body(
    const float* __restrict__ Ag,
    const float* __restrict__ Bg,
    float* __restrict__ Cg,
    const float* __restrict__ Rg,
    int ldc,
    const float* __restrict__ mu_p,
    const float* __restrict__ rs_p,
    const float* __restrict__ lnw,
    const float* __restrict__ lnb)
{
    constexpr int MT = 64;
    constexpr int MTILES = 2;
    constexpr int NCHUNK = KTOT / 32;
    constexpr int STAGE_U32 = MT*40 + 16*136*2;   // 6912
    extern __shared__ __align__(16) float smg[];
    u32* sbase = (u32*)smg;

    int tid = threadIdx.x;
    int lane = tid & 31, wid = tid >> 5;
    int g = lane >> 2, t = lane & 3;
    int warp_m = (wid >> 2) * 32;
    int warp_n = (wid & 3) * 32;

    float acc[MTILES][4][4];
    #pragma unroll
    for (int i = 0; i < MTILES; i++)
        #pragma unroll
        for (int j = 0; j < 4; j++)
            #pragma unroll
            for (int r = 0; r < 4; r++) acc[i][j][r] = 0.0f;

    int a_row = tid >> 2;            // 0..63
    int a_c0  = (tid & 3) * 8;       // 0,8,16,24
    int b_kp  = tid >> 4;            // 0..15
    int b_n0  = (tid & 15) * 8;      // 0..120

    float a_mu = 0.0f, a_rs = 1.0f;
    if (LNA) { a_mu = mu_p[a_row]; a_rs = rs_p[a_row]; }

    float4 aReg[2];
    float4 bReg[4];

    auto loadG = [&](int k0) {
        #pragma unroll
        for (int i = 0; i < 2; i++)
            aReg[i] = *(const float4*)&Ag[(size_t)a_row*LDA_G + k0 + a_c0 + i*4];
        const float* B0 = &Bg[(size_t)(k0 + 2*b_kp)*LDB_G + b_n0];
        bReg[0] = *(const float4*)B0;
        bReg[1] = *(const float4*)(B0 + 4);
        bReg[2] = *(const float4*)(B0 + LDB_G);
        bReg[3] = *(const float4*)(B0 + LDB_G + 4);
    };
    auto cvtStore = [&](int s, int k0) {
        u32* AsH = sbase + s*STAGE_U32;
        u32* AsL = AsH + MT*20;
        u32* BsH = AsL + MT*20;
        u32* BsL = BsH + 16*136;
        #pragma unroll
        for (int i = 0; i < 2; i++) {
            int c = a_c0 + i*4;
            float4 a4 = aReg[i];
            if (LNA) {
                float4 w4 = *(const float4*)&lnw[k0 + c];
                float4 b4 = *(const float4*)&lnb[k0 + c];
                a4.x = (a4.x - a_mu) * a_rs * w4.x + b4.x;
                a4.y = (a4.y - a_mu) * a_rs * w4.y + b4.y;
                a4.z = (a4.z - a_mu) * a_rs * w4.z + b4.z;
                a4.w = (a4.w - a_mu) * a_rs * w4.w + b4.w;
            }
            u32 h01, l01, h23, l23;
            bfsplit(a4.x, a4.y, h01, l01);
            bfsplit(a4.z, a4.w, h23, l23);
            int cu = c >> 1;
            *(uint2*)&AsH[a_row*20 + cu] = make_uint2(h01, h23);
            *(uint2*)&AsL[a_row*20 + cu] = make_uint2(l01, l23);
        }
        u32 h[8], l[8];
        bfsplit(bReg[0].x, bReg[2].x, h[0], l[0]);
        bfsplit(bReg[0].y, bReg[2].y, h[1], l[1]);
        bfsplit(bReg[0].z, bReg[2].z, h[2], l[2]);
        bfsplit(bReg[0].w, bReg[2].w, h[3], l[3]);
        bfsplit(bReg[1].x, bReg[3].x, h[4], l[4]);
        bfsplit(bReg[1].y, bReg[3].y, h[5], l[5]);
        bfsplit(bReg[1].z, bReg[3].z, h[6], l[6]);
        bfsplit(bReg[1].w, bReg[3].w, h[7], l[7]);
        u32* dh = &BsH[b_kp*136 + b_n0];
        u32* dl = &BsL[b_kp*136 + b_n0];
        *(uint4*)dh       = make_uint4(h[0], h[1], h[2], h[3]);
        *(uint4*)(dh + 4) = make_uint4(h[4], h[5], h[6], h[7]);
        *(uint4*)dl       = make_uint4(l[0], l[1], l[2], l[3]);
        *(uint4*)(dl + 4) = make_uint4(l[4], l[5], l[6], l[7]);
    };

    loadG(0);
    cvtStore(0, 0);
    __syncthreads();

    for (int c = 0; c < NCHUNK; c++) {
        if (c + 1 < NCHUNK) loadG((c+1)*32);

        u32* AsH = sbase + (c & 1)*STAGE_U32;
        u32* AsL = AsH + MT*20;
        u32* BsH = AsL + MT*20;
        u32* BsL = BsH + 16*136;
        #pragma unroll
        for (int kk = 0; kk < 2; kk++) {
            int kp = kk*8;
            u32 bh[4][2], bl[4][2];
            #pragma unroll
            for (int nt = 0; nt < 4; nt++) {
                int n = warp_n + nt*8 + g;
                bh[nt][0] = BsH[(kp + t)*136 + n];
                bh[nt][1] = BsH[(kp + t + 4)*136 + n];
                bl[nt][0] = BsL[(kp + t)*136 + n];
                bl[nt][1] = BsL[(kp + t + 4)*136 + n];
            }
            #pragma unroll
            for (int mt = 0; mt < MTILES; mt++) {
                int m = warp_m + mt*16;
                u32 ah[4], al[4];
                ah[0] = AsH[(m + g)*20 + kp + t];
                ah[1] = AsH[(m + g + 8)*20 + kp + t];
                ah[2] = AsH[(m + g)*20 + kp + t + 4];
                ah[3] = AsH[(m + g + 8)*20 + kp + t + 4];
                al[0] = AsL[(m + g)*20 + kp + t];
                al[1] = AsL[(m + g + 8)*20 + kp + t];
                al[2] = AsL[(m + g)*20 + kp + t + 4];
                al[3] = AsL[(m + g + 8)*20 + kp + t + 4];
                #pragma unroll
                for (int nt = 0; nt < 4; nt++) {
                    mma_bf16(acc[mt][nt], ah[0], ah[1], ah[2], ah[3], bh[nt][0], bh[nt][1]);
                    mma_bf16(acc[mt][nt], ah[0], ah[1], ah[2], ah[3], bl[nt][0], bl[nt][1]);
                    mma_bf16(acc[mt][nt], al[0], al[1], al[2], al[3], bh[nt][0], bh[nt][1]);
                }
            }
        }
        if (c + 1 < NCHUNK) cvtStore((c+1) & 1, (c+1)*32);
        __syncthreads();
    }

    #pragma unroll
    for (int mt = 0; mt < MTILES; mt++) {
        #pragma unroll
        for (int nt = 0; nt < 4; nt++) {
            int r0 = warp_m + mt*16 + g;
            int col = warp_n + nt*8 + 2*t;
            float* d0 = Cg + (size_t)r0*ldc + col;
            float* d1 = d0 + 8*ldc;
            float c0 = acc[mt][nt][0], c1 = acc[mt][nt][1];
            float c2 = acc[mt][nt][2], c3 = acc[mt][nt][3];
            if (RESID) {
                const float* s0 = Rg + (size_t)r0*ldc + col;
                const float* s1 = s0 + 8*ldc;
                float2 t0 = *(const float2*)s0;
                float2 t1 = *(const float2*)s1;
                c0 += t0.x; c1 += t0.y; c2 += t1.x; c3 += t1.y;
            }
            *(float2*)d0 = make_float2(c0, c1);
            *(float2*)d1 = make_float2(c2, c3);
        }
    }
}

#define GEMM_SMEM ((64*40 + 16*136*2) * 4 * 2)   // 55296 B (2 stages)

// ---------------- stage 2: QKV gemm (LN fused into A load) ----------------
__global__ void __launch_bounds__(256, 2)
gemm_qkv(const float* __restrict__ tok,
         const float* __restrict__ lnw, const float* __restrict__ lnb,
         const float* __restrict__ wq,
         const float* __restrict__ wk,
         const float* __restrict__ wv) {
    int m0 = blockIdx.x * 64;
    int n0 = blockIdx.y * 128;
    const float* Bsrc; int nb;
    if (n0 < 256)      { Bsrc = wq; nb = n0; }
    else if (n0 < 512) { Bsrc = wk; nb = n0 - 256; }
    else               { Bsrc = wv; nb = n0 - 512; }
    gemm_tc_body<128, 128, 256, false, true>(
        tok + (size_t)m0*128, Bsrc + nb,
        g_y + (size_t)m0*768 + n0, nullptr, 768,
        g_mu + m0, g_rs + m0, lnw, lnb);
}

// ---------------- stage 4: output gemm + residual ----------------
__global__ void __launch_bounds__(256, 2)
gemm_out(const float* __restrict__ wo,
         const float* __restrict__ tok,
         float* __restrict__ out) {
    int m0 = blockIdx.x * 64;
    gemm_tc_body<256, 256, 128, true, false>(
        g_ho + (size_t)m0*256, wo,
        out + (size_t)m0*128, tok + (size_t)m0*128, 128,
        nullptr, nullptr, nullptr, nullptr);
}

// ---------------- stage 3: banded differential attention ----------------
// 6-sigma band; m1 PV restricted to the m1 window (dropped terms < 1e-8 rel).
__global__ void __launch_bounds__(512, 1)
attn_kernel(const float* __restrict__ lq1, const float* __restrict__ lk1,
            const float* __restrict__ lq2, const float* __restrict__ lk2,
            const float* __restrict__ sigS, const float* __restrict__ sigN,
            const float* __restrict__ hnw,  const float* __restrict__ hnb) {
    extern __shared__ float sm[];
    float* Ksm = sm;
    float* Vsm = Ksm + KROWS*KLD;
    float* Qsm = Vsm + KROWS*64;
    u64*   Pb  = (u64*)(Qsm + QT*64);
    __shared__ float s_lam;

    int tid = threadIdx.x;
    int bh  = blockIdx.y;
    int b   = bh >> 2;
    int h   = bh & 3;
    int q0  = blockIdx.x * QT;

    float ss = fmaxf(sigS[0], 1.0f), sn = fmaxf(sigN[0], 1.0f);
    float c1 = -0.5f / (ss*ss);
    float c2 = -0.5f / (sn*sn);
    int Wn = (int)ceilf(6.0f * fmaxf(ss, sn)); if (Wn > W_MAX) Wn = W_MAX;
    int W1 = (int)ceilf(6.0f * ss);            if (W1 > W_MAX) W1 = W_MAX;

    int blo = q0 - Wn;          if (blo < 0) blo = 0;
    int bhi = q0 + QT - 1 + Wn; if (bhi > TT-1) bhi = TT-1;
    int nrows = bhi - blo + 1;

    const float* ybase = g_y + (size_t)(b*TT) * 768;

    for (int idx = tid; idx < nrows*64; idx += 512) {
        int r = idx >> 6, d = idx & 63;
        const float* row = ybase + (size_t)(blo + r)*768 + h*64;
        Ksm[r*KLD + d] = row[256 + d];
        float v = row[512 + d];
        int dd = (d < 32) ? (2*d) : (2*(d-32) + 1);
        Vsm[r*64 + dd] = v;
    }
    for (int idx = tid; idx < QT*64; idx += 512) {
        int r = idx >> 6, d = idx & 63;
        Qsm[idx] = ybase[(size_t)(q0 + r)*768 + h*64 + d];
    }
    if (tid == 0) {
        float d1 = 0.0f, d2 = 0.0f;
        #pragma unroll
        for (int i = 0; i < 32; i++) { d1 += lq1[i]*lk1[i]; d2 += lq2[i]*lk2[i]; }
        s_lam = __expf(d1) - __expf(d2) + LAMBDA_INIT;
    }
    __syncthreads();
    float lam = s_lam;

    int w = tid >> 5, lane = tid & 31;
    int i0 = q0 + w*QW;
    int jlo = i0 - Wn;           if (jlo < blo) jlo = blo;
    int jhi = i0 + QW - 1 + Wn;  if (jhi > bhi) jhi = bhi;
    int m1lo = i0 - W1, m1hi = i0 + QW - 1 + W1;

    u64* p1w = Pb + w*256;
    u64* p2w = p1w + 128;

    u64 o1x[4], o1y[4], o2x[4], o2y[4];
    float l1[QW], l2[QW];
    #pragma unroll
    for (int i = 0; i < 4; i++) { o1x[i]=0ull; o1y[i]=0ull; o2x[i]=0ull; o2y[i]=0ull; }
    #pragma unroll
    for (int q = 0; q < QW; q++) { l1[q] = 0.0f; l2[q] = 0.0f; }

    for (int jc = jlo; jc <= jhi; jc += 32) {
        bool doM1 = (jc <= m1hi) && (jc + 31 >= m1lo);
        int j = jc + lane;
        bool valid = (j <= jhi);
        int r = (valid ? j : jhi) - blo;
        const ulonglong2* kr = (const ulonglong2*)(Ksm + r*KLD);
        float relb = (float)(j - i0);

        u64 a2[QW];
        #pragma unroll
        for (int q = 0; q < QW; q++) a2[q] = 0ull;
        #pragma unroll
        for (int dc = 8; dc < 16; dc++) {
            ulonglong2 k2 = kr[dc];
            #pragma unroll
            for (int q = 0; q < QW; q++) {
                ulonglong2 q2 = *(const ulonglong2*)(Qsm + (w*QW + q)*64 + dc*4);
                a2[q] = f2fma(k2.x, q2.x, a2[q]);
                a2[q] = f2fma(k2.y, q2.y, a2[q]);
            }
        }
        float e2[QW];
        #pragma unroll
        for (int q = 0; q < QW; q++) {
            float rel = relb - (float)q, rr = rel*rel;
            float lo, hi; up2(a2[q], lo, hi);
            float s = (lo + hi)*SCALE + rr*c2;
            e2[q] = valid ? __expf(s) : 0.0f;
            l2[q] += e2[q];
        }
        ((ulonglong2*)p2w)[lane*2]     = make_ulonglong2(pk2(e2[0],e2[1]), pk2(e2[2],e2[3]));
        ((ulonglong2*)p2w)[lane*2 + 1] = make_ulonglong2(pk2(e2[4],e2[5]), pk2(e2[6],e2[7]));

        if (doM1) {
            u64 a1[QW];
            #pragma unroll
            for (int q = 0; q < QW; q++) a1[q] = 0ull;
            #pragma unroll
            for (int dc = 0; dc < 8; dc++) {
                ulonglong2 k2 = kr[dc];
                #pragma unroll
                for (int q = 0; q < QW; q++) {
                    ulonglong2 q2 = *(const ulonglong2*)(Qsm + (w*QW + q)*64 + dc*4);
                    a1[q] = f2fma(k2.x, q2.x, a1[q]);
                    a1[q] = f2fma(k2.y, q2.y, a1[q]);
                }
            }
            float e1[QW];
            #pragma unroll
            for (int q = 0; q < QW; q++) {
                float rel = relb - (float)q, rr = rel*rel;
                float lo, hi; up2(a1[q], lo, hi);
                float s = (lo + hi)*SCALE + rr*c1;
                e1[q] = valid ? __expf(s) : 0.0f;
                l1[q] += e1[q];
            }
            ((ulonglong2*)p1w)[lane*2]     = make_ulonglong2(pk2(e1[0],e1[1]), pk2(e1[2],e1[3]));
            ((ulonglong2*)p1w)[lane*2 + 1] = make_ulonglong2(pk2(e1[4],e1[5]), pk2(e1[6],e1[7]));
        }
        __syncwarp();

        int cnt = jhi - jc + 1; if (cnt > 32) cnt = 32;
        const float2* vb = (const float2*)(Vsm + (jc - blo)*64);
        const ulonglong2* P1 = (const ulonglong2*)p1w;
        const ulonglong2* P2 = (const ulonglong2*)p2w;
        // matrix-2 PV over the full chunk
        for (int jj = 0; jj < cnt; jj++) {
            float2 v = vb[jj*32 + lane];
            u64 vx = pk2(v.x, v.x), vy = pk2(v.y, v.y);
            ulonglong2 qa = P2[jj*2], qb = P2[jj*2 + 1];
            o2x[0] = f2fma(qa.x, vx, o2x[0]);  o2y[0] = f2fma(qa.x, vy, o2y[0]);
            o2x[1] = f2fma(qa.y, vx, o2x[1]);  o2y[1] = f2fma(qa.y, vy, o2y[1]);
            o2x[2] = f2fma(qb.x, vx, o2x[2]);  o2y[2] = f2fma(qb.x, vy, o2y[2]);
            o2x[3] = f2fma(qb.y, vx, o2x[3]);  o2y[3] = f2fma(qb.y, vy, o2y[3]);
        }
        // matrix-1 PV only over the m1 window
        if (doM1) {
            int j0 = m1lo - jc; if (j0 < 0) j0 = 0;
            int j1 = m1hi - jc + 1; if (j1 > cnt) j1 = cnt;
            for (int jj = j0; jj < j1; jj++) {
                float2 v = vb[jj*32 + lane];
                u64 vx = pk2(v.x, v.x), vy = pk2(v.y, v.y);
                ulonglong2 pa = P1[jj*2], pb = P1[jj*2 + 1];
                o1x[0] = f2fma(pa.x, vx, o1x[0]);  o1y[0] = f2fma(pa.x, vy, o1y[0]);
                o1x[1] = f2fma(pa.y, vx, o1x[1]);  o1y[1] = f2fma(pa.y, vy, o1y[1]);
                o1x[2] = f2fma(pb.x, vx, o1x[2]);  o1y[2] = f2fma(pb.x, vy, o1y[2]);
                o1x[3] = f2fma(pb.y, vx, o1x[3]);  o1y[3] = f2fma(pb.y, vy, o1y[3]);
            }
        }
        __syncwarp();
    }

    float hw0 = hnw[lane], hw1 = hnw[lane+32];
    float hb0 = hnb[lane], hb1 = hnb[lane+32];
    float post = 1.0f - LAMBDA_INIT;
    #pragma unroll
    for (int qp = 0; qp < 4; qp++) {
        float x1a, x1b, y1a, y1b, x2a, x2b, y2a, y2b;
        up2(o1x[qp], x1a, x1b);  up2(o1y[qp], y1a, y1b);
        up2(o2x[qp], x2a, x2b);  up2(o2y[qp], y2a, y2b);
        #pragma unroll
        for (int sub = 0; sub < 2; sub++) {
            int q = qp*2 + sub;
            float x1 = sub ? x1b : x1a, y1 = sub ? y1b : y1a;
            float x2 = sub ? x2b : x2a, y2 = sub ? y2b : y2a;
            float L1 = warpsum(l1[q]);
            float L2 = warpsum(l2[q]);
            float il1 = 1.0f / L1;
            float il2 = lam  / L2;
            float ox = x1*il1 - x2*il2;
            float oy = y1*il1 - y2*il2;
            float s  = warpsum(ox + oy);
            float sq = warpsum(ox*ox + oy*oy);
            float mu  = s * (1.0f/64.0f);
            float var = sq * (1.0f/64.0f) - mu*mu;
            float rs  = rsqrtf(var + LN_EPS);
            float y0 = ((ox - mu)*rs*hw0 + hb0) * post;
            float y1o = ((oy - mu)*rs*hw1 + hb1) * post;
            int i = i0 + q;
            float* dst = g_ho + (size_t)(b*TT + i)*256 + h*64;
            dst[lane]      = y0;
            dst[lane + 32] = y1o;
        }
    }
}

// ---------------- launch ----------------
extern "C" void kernel_launch(void* const* d_in, const int* in_sizes, int n_in,
                              void* d_out, int out_size) {
    const float* tokens = (const float*)d_in[0];
    const float* ln_w   = (const float*)d_in[1];
    const float* ln_b   = (const float*)d_in[2];
    const float* wq     = (const float*)d_in[3];
    const float* wk     = (const float*)d_in[4];
    const float* wv     = (const float*)d_in[5];
    const float* wo     = (const float*)d_in[6];
    const float* lq1    = (const float*)d_in[7];
    const float* lk1    = (const float*)d_in[8];
    const float* lq2    = (const float*)d_in[9];
    const float* lk2    = (const float*)d_in[10];
    const float* sigS   = (const float*)d_in[11];
    const float* sigN   = (const float*)d_in[12];
    const float* hnw    = (const float*)d_in[13];
    const float* hnb    = (const float*)d_in[14];
    float* out = (float*)d_out;

    const size_t attn_smem = (size_t)(KROWS*KLD + KROWS*64 + QT*64) * sizeof(float)
                           + (size_t)NW * 256 * sizeof(u64);
    cudaFuncSetAttribute(attn_kernel, cudaFuncAttributeMaxDynamicSharedMemorySize, (int)attn_smem);
    cudaFuncSetAttribute(gemm_qkv, cudaFuncAttributeMaxDynamicSharedMemorySize, GEMM_SMEM);
    cudaFuncSetAttribute(gemm_out, cudaFuncAttributeMaxDynamicSharedMemorySize, GEMM_SMEM);

    ln_stats<<<NTOK/8, 256>>>(tokens);
    gemm_qkv<<<dim3(NTOK/64, 6), 256, GEMM_SMEM>>>(tokens, ln_w, ln_b, wq, wk, wv);
    attn_kernel<<<dim3(TT/QT, BB*HH), 512, attn_smem>>>(lq1, lk1, lq2, lk2, sigS, sigN, hnw, hnb);
    gemm_out<<<NTOK/64, 256, GEMM_SMEM>>>(wo, tokens, out);
}

// round 14
// speedup vs baseline: 1.1727x; 1.1727x over previous
#include <cuda_runtime.h>
#include <math.h>

// ---------------- problem constants ----------------
#define TT 2048
#define BB 8
#define DD 128
#define HH 4
#define NTOK (BB*TT)          // 16384
#define SCALE 0.17677669529663687f   // 1/sqrt(32)
#define LAMBDA_INIT 0.8f
#define LN_EPS 1e-5f

#define W_MAX 80
#define QTA 128               // queries per attention CTA
#define KRP 304               // padded K/V band rows (covers 127+2*80, tile-aligned)
#define KPL 36                // K row stride in u32 (32 pairs + pad, banks 4g+t)
#define VLD 164               // V_T row stride in u32 (152 jp capacity, banks 4g+t)

typedef unsigned long long u64;
typedef unsigned int u32;

// ---------------- scratch ----------------
__device__ float g_mu[NTOK];
__device__ float g_rs[NTOK];
__device__ float g_y [NTOK*768];
__device__ float g_ho[NTOK*256];

// ---------------- helpers ----------------
__device__ __forceinline__ float warpsum(float v) {
    #pragma unroll
    for (int o = 16; o; o >>= 1) v += __shfl_xor_sync(0xffffffffu, v, o);
    return v;
}
__device__ __forceinline__ float quadsum(float v) {
    v += __shfl_xor_sync(0xffffffffu, v, 1);
    v += __shfl_xor_sync(0xffffffffu, v, 2);
    return v;
}
__device__ __forceinline__ u32 bfpack(float upper, float lower) {
    u32 r; asm("cvt.rn.bf16x2.f32 %0, %1, %2;" : "=r"(r) : "f"(upper), "f"(lower));
    return r;
}
// split (x0 = even elem, x1 = odd elem) into hi bf16x2 + residual bf16x2
__device__ __forceinline__ void bfsplit(float x0, float x1, u32& h, u32& l) {
    h = bfpack(x1, x0);
    float f0 = __uint_as_float(h << 16);
    float f1 = __uint_as_float(h & 0xFFFF0000u);
    l = bfpack(x1 - f1, x0 - f0);
}
__device__ __forceinline__ void mma_bf16(float* c, const u32* a, u32 b0, u32 b1) {
    asm volatile(
        "mma.sync.aligned.m16n8k16.row.col.f32.bf16.bf16.f32 "
        "{%0,%1,%2,%3}, {%4,%5,%6,%7}, {%8,%9}, {%0,%1,%2,%3};"
        : "+f"(c[0]), "+f"(c[1]), "+f"(c[2]), "+f"(c[3])
        : "r"(a[0]), "r"(a[1]), "r"(a[2]), "r"(a[3]), "r"(b0), "r"(b1));
}

// ---------------- stage 1: layernorm stats only ----------------
__global__ void ln_stats(const float* __restrict__ tok) {
    int t = blockIdx.x * 8 + (threadIdx.x >> 5);
    int lane = threadIdx.x & 31;
    const float4* src = (const float4*)(tok + (size_t)t * DD);
    float4 x = src[lane];
    float s  = x.x + x.y + x.z + x.w;
    float sq = x.x*x.x + x.y*x.y + x.z*x.z + x.w*x.w;
    s  = warpsum(s);
    sq = warpsum(sq);
    float mu  = s * (1.0f/128.0f);
    float var = sq * (1.0f/128.0f) - mu*mu;
    if (lane == 0) {
        g_mu[t] = mu;
        g_rs[t] = rsqrtf(var + LN_EPS);
    }
}

// ---------------- 3xBF16 TC GEMM, MT=64 tile, 2-stage double buffer ----------------
template<int KTOT, int LDA_G, int LDB_G, bool RESID, bool LNA>
__device__ __forceinline__ void gemm_tc_body(
    const float* __restrict__ Ag,
    const float* __restrict__ Bg,
    float* __restrict__ Cg,
    const float* __restrict__ Rg,
    int ldc,
    const float* __restrict__ mu_p,
    const float* __restrict__ rs_p,
    const float* __restrict__ lnw,
    const float* __restrict__ lnb)
{
    constexpr int MT = 64;
    constexpr int MTILES = 2;
    constexpr int NCHUNK = KTOT / 32;
    constexpr int STAGE_U32 = MT*40 + 16*136*2;
    extern __shared__ __align__(16) float smg[];
    u32* sbase = (u32*)smg;

    int tid = threadIdx.x;
    int lane = tid & 31, wid = tid >> 5;
    int g = lane >> 2, t = lane & 3;
    int warp_m = (wid >> 2) * 32;
    int warp_n = (wid & 3) * 32;

    float acc[MTILES][4][4];
    #pragma unroll
    for (int i = 0; i < MTILES; i++)
        #pragma unroll
        for (int j = 0; j < 4; j++)
            #pragma unroll
            for (int r = 0; r < 4; r++) acc[i][j][r] = 0.0f;

    int a_row = tid >> 2;
    int a_c0  = (tid & 3) * 8;
    int b_kp  = tid >> 4;
    int b_n0  = (tid & 15) * 8;

    float a_mu = 0.0f, a_rs = 1.0f;
    if (LNA) { a_mu = mu_p[a_row]; a_rs = rs_p[a_row]; }

    float4 aReg[2];
    float4 bReg[4];

    auto loadG = [&](int k0) {
        #pragma unroll
        for (int i = 0; i < 2; i++)
            aReg[i] = *(const float4*)&Ag[(size_t)a_row*LDA_G + k0 + a_c0 + i*4];
        const float* B0 = &Bg[(size_t)(k0 + 2*b_kp)*LDB_G + b_n0];
        bReg[0] = *(const float4*)B0;
        bReg[1] = *(const float4*)(B0 + 4);
        bReg[2] = *(const float4*)(B0 + LDB_G);
        bReg[3] = *(const float4*)(B0 + LDB_G + 4);
    };
    auto cvtStore = [&](int s, int k0) {
        u32* AsH = sbase + s*STAGE_U32;
        u32* AsL = AsH + MT*20;
        u32* BsH = AsL + MT*20;
        u32* BsL = BsH + 16*136;
        #pragma unroll
        for (int i = 0; i < 2; i++) {
            int c = a_c0 + i*4;
            float4 a4 = aReg[i];
            if (LNA) {
                float4 w4 = *(const float4*)&lnw[k0 + c];
                float4 b4 = *(const float4*)&lnb[k0 + c];
                a4.x = (a4.x - a_mu) * a_rs * w4.x + b4.x;
                a4.y = (a4.y - a_mu) * a_rs * w4.y + b4.y;
                a4.z = (a4.z - a_mu) * a_rs * w4.z + b4.z;
                a4.w = (a4.w - a_mu) * a_rs * w4.w + b4.w;
            }
            u32 h01, l01, h23, l23;
            bfsplit(a4.x, a4.y, h01, l01);
            bfsplit(a4.z, a4.w, h23, l23);
            int cu = c >> 1;
            *(uint2*)&AsH[a_row*20 + cu] = make_uint2(h01, h23);
            *(uint2*)&AsL[a_row*20 + cu] = make_uint2(l01, l23);
        }
        u32 h[8], l[8];
        bfsplit(bReg[0].x, bReg[2].x, h[0], l[0]);
        bfsplit(bReg[0].y, bReg[2].y, h[1], l[1]);
        bfsplit(bReg[0].z, bReg[2].z, h[2], l[2]);
        bfsplit(bReg[0].w, bReg[2].w, h[3], l[3]);
        bfsplit(bReg[1].x, bReg[3].x, h[4], l[4]);
        bfsplit(bReg[1].y, bReg[3].y, h[5], l[5]);
        bfsplit(bReg[1].z, bReg[3].z, h[6], l[6]);
        bfsplit(bReg[1].w, bReg[3].w, h[7], l[7]);
        u32* dh = &BsH[b_kp*136 + b_n0];
        u32* dl = &BsL[b_kp*136 + b_n0];
        *(uint4*)dh       = make_uint4(h[0], h[1], h[2], h[3]);
        *(uint4*)(dh + 4) = make_uint4(h[4], h[5], h[6], h[7]);
        *(uint4*)dl       = make_uint4(l[0], l[1], l[2], l[3]);
        *(uint4*)(dl + 4) = make_uint4(l[4], l[5], l[6], l[7]);
    };

    loadG(0);
    cvtStore(0, 0);
    __syncthreads();

    for (int c = 0; c < NCHUNK; c++) {
        if (c + 1 < NCHUNK) loadG((c+1)*32);

        u32* AsH = sbase + (c & 1)*STAGE_U32;
        u32* AsL = AsH + MT*20;
        u32* BsH = AsL + MT*20;
        u32* BsL = BsH + 16*136;
        #pragma unroll
        for (int kk = 0; kk < 2; kk++) {
            int kp = kk*8;
            u32 bh[4][2], bl[4][2];
            #pragma unroll
            for (int nt = 0; nt < 4; nt++) {
                int n = warp_n + nt*8 + g;
                bh[nt][0] = BsH[(kp + t)*136 + n];
                bh[nt][1] = BsH[(kp + t + 4)*136 + n];
                bl[nt][0] = BsL[(kp + t)*136 + n];
                bl[nt][1] = BsL[(kp + t + 4)*136 + n];
            }
            #pragma unroll
            for (int mt = 0; mt < MTILES; mt++) {
                int m = warp_m + mt*16;
                u32 ah[4], al[4];
                ah[0] = AsH[(m + g)*20 + kp + t];
                ah[1] = AsH[(m + g + 8)*20 + kp + t];
                ah[2] = AsH[(m + g)*20 + kp + t + 4];
                ah[3] = AsH[(m + g + 8)*20 + kp + t + 4];
                al[0] = AsL[(m + g)*20 + kp + t];
                al[1] = AsL[(m + g + 8)*20 + kp + t];
                al[2] = AsL[(m + g)*20 + kp + t + 4];
                al[3] = AsL[(m + g + 8)*20 + kp + t + 4];
                #pragma unroll
                for (int nt = 0; nt < 4; nt++) {
                    mma_bf16(acc[mt][nt], ah, bh[nt][0], bh[nt][1]);
                    mma_bf16(acc[mt][nt], ah, bl[nt][0], bl[nt][1]);
                    mma_bf16(acc[mt][nt], al, bh[nt][0], bh[nt][1]);
                }
            }
        }
        if (c + 1 < NCHUNK) cvtStore((c+1) & 1, (c+1)*32);
        __syncthreads();
    }

    #pragma unroll
    for (int mt = 0; mt < MTILES; mt++) {
        #pragma unroll
        for (int nt = 0; nt < 4; nt++) {
            int r0 = warp_m + mt*16 + g;
            int col = warp_n + nt*8 + 2*t;
            float* d0 = Cg + (size_t)r0*ldc + col;
            float* d1 = d0 + 8*ldc;
            float c0 = acc[mt][nt][0], c1 = acc[mt][nt][1];
            float c2 = acc[mt][nt][2], c3 = acc[mt][nt][3];
            if (RESID) {
                const float* s0 = Rg + (size_t)r0*ldc + col;
                const float* s1 = s0 + 8*ldc;
                float2 t0 = *(const float2*)s0;
                float2 t1 = *(const float2*)s1;
                c0 += t0.x; c1 += t0.y; c2 += t1.x; c3 += t1.y;
            }
            *(float2*)d0 = make_float2(c0, c1);
            *(float2*)d1 = make_float2(c2, c3);
        }
    }
}

#define GEMM_SMEM ((64*40 + 16*136*2) * 4 * 2)

__global__ void __launch_bounds__(256, 2)
gemm_qkv(const float* __restrict__ tok,
         const float* __restrict__ lnw, const float* __restrict__ lnb,
         const float* __restrict__ wq,
         const float* __restrict__ wk,
         const float* __restrict__ wv) {
    int m0 = blockIdx.x * 64;
    int n0 = blockIdx.y * 128;
    const float* Bsrc; int nb;
    if (n0 < 256)      { Bsrc = wq; nb = n0; }
    else if (n0 < 512) { Bsrc = wk; nb = n0 - 256; }
    else               { Bsrc = wv; nb = n0 - 512; }
    gemm_tc_body<128, 128, 256, false, true>(
        tok + (size_t)m0*128, Bsrc + nb,
        g_y + (size_t)m0*768 + n0, nullptr, 768,
        g_mu + m0, g_rs + m0, lnw, lnb);
}

__global__ void __launch_bounds__(256, 2)
gemm_out(const float* __restrict__ wo,
         const float* __restrict__ tok,
         float* __restrict__ out) {
    int m0 = blockIdx.x * 64;
    gemm_tc_body<256, 256, 128, true, false>(
        g_ho + (size_t)m0*256, wo,
        out + (size_t)m0*128, tok + (size_t)m0*128, 128,
        nullptr, nullptr, nullptr, nullptr);
}

// ---------------- stage 3: tensor-core banded differential attention ----------------
// Warp = 16 queries. Scores: bf16 2-term mma (Q in register A-frags, K hi/lo in smem).
// Softmax in registers via C->A fragment repack. PV: 3-term bf16 mma with V_T in smem.
// 6-sigma band; out-of-band columns killed by Gaussian bias; rows >= nrows zeroed+masked.
#define ATTN_SMEM ((2*KRP*KPL + 2*64*VLD) * 4)

__global__ void __launch_bounds__(256, 1)
attn_kernel(const float* __restrict__ lq1, const float* __restrict__ lk1,
            const float* __restrict__ lq2, const float* __restrict__ lk2,
            const float* __restrict__ sigS, const float* __restrict__ sigN,
            const float* __restrict__ hnw,  const float* __restrict__ hnb) {
    extern __shared__ __align__(16) u32 smu[];
    u32* Kh = smu;                  // [KRP][KPL]
    u32* Kl = Kh + KRP*KPL;
    u32* Vh = Kl + KRP*KPL;         // [64][VLD] d-major, bf16x2 j-pairs
    u32* Vl = Vh + 64*VLD;
    __shared__ float s_lam;

    int tid = threadIdx.x;
    int bh  = blockIdx.y;
    int b   = bh >> 2;
    int h   = bh & 3;
    int q0  = blockIdx.x * QTA;

    float ss = fmaxf(sigS[0], 1.0f), sn = fmaxf(sigN[0], 1.0f);
    float c1 = -0.5f / (ss*ss);
    float c2 = -0.5f / (sn*sn);
    int Wn = (int)ceilf(6.0f * fmaxf(ss, sn)); if (Wn > W_MAX) Wn = W_MAX;
    int W1 = (int)ceilf(6.0f * ss);            if (W1 > W_MAX) W1 = W_MAX;

    int blo = q0 - Wn;            if (blo < 0) blo = 0;
    int bhi = q0 + QTA - 1 + Wn;  if (bhi > TT-1) bhi = TT-1;
    int nrows = bhi - blo + 1;

    const float* ybase = g_y + (size_t)(b*TT) * 768;

    // --- load K band (hi/lo bf16x2 pairs), zero-fill padding rows ---
    for (int idx = tid; idx < KRP*16; idx += 256) {
        int r = idx >> 4, grp = idx & 15;
        u32 h0 = 0, l0 = 0, h1 = 0, l1 = 0;
        if (r < nrows) {
            float4 v4 = *(const float4*)(ybase + (size_t)(blo + r)*768 + h*64 + 256 + grp*4);
            bfsplit(v4.x, v4.y, h0, l0);
            bfsplit(v4.z, v4.w, h1, l1);
        }
        Kh[r*KPL + grp*2]     = h0;
        Kh[r*KPL + grp*2 + 1] = h1;
        Kl[r*KPL + grp*2]     = l0;
        Kl[r*KPL + grp*2 + 1] = l1;
    }
    // --- load V transposed (d-major, j-pairs packed bf16x2) ---
    for (int idx = tid; idx < 152*16; idx += 256) {
        int jp = idx >> 4, dg = idx & 15;
        int r0 = 2*jp, r1 = 2*jp + 1;
        float4 va = make_float4(0,0,0,0), vb = make_float4(0,0,0,0);
        if (r0 < nrows) va = *(const float4*)(ybase + (size_t)(blo + r0)*768 + h*64 + 512 + dg*4);
        if (r1 < nrows) vb = *(const float4*)(ybase + (size_t)(blo + r1)*768 + h*64 + 512 + dg*4);
        u32 hh, ll;
        bfsplit(va.x, vb.x, hh, ll); Vh[(dg*4+0)*VLD + jp] = hh; Vl[(dg*4+0)*VLD + jp] = ll;
        bfsplit(va.y, vb.y, hh, ll); Vh[(dg*4+1)*VLD + jp] = hh; Vl[(dg*4+1)*VLD + jp] = ll;
        bfsplit(va.z, vb.z, hh, ll); Vh[(dg*4+2)*VLD + jp] = hh; Vl[(dg*4+2)*VLD + jp] = ll;
        bfsplit(va.w, vb.w, hh, ll); Vh[(dg*4+3)*VLD + jp] = hh; Vl[(dg*4+3)*VLD + jp] = ll;
    }
    if (tid == 0) {
        float d1 = 0.0f, d2 = 0.0f;
        #pragma unroll
        for (int i = 0; i < 32; i++) { d1 += lq1[i]*lk1[i]; d2 += lq2[i]*lk2[i]; }
        s_lam = __expf(d1) - __expf(d2) + LAMBDA_INIT;
    }
    __syncthreads();
    float lam = s_lam;

    int w = tid >> 5, lane = tid & 31;
    int g = lane >> 2, t = lane & 3;
    int i0 = q0 + w*16;

    // --- Q A-frags in registers (hi/lo, 2 matrices x 2 ksteps) ---
    u32 QfH[2][2][4], QfL[2][2][4];
    {
        const float* qr0 = ybase + (size_t)(i0 + g)*768 + h*64;
        const float* qr1 = qr0 + (size_t)8*768;
        #pragma unroll
        for (int m = 0; m < 2; m++) {
            #pragma unroll
            for (int s = 0; s < 2; s++) {
                int d0 = m*32 + s*16 + 2*t;
                float2 x0 = *(const float2*)(qr0 + d0);
                float2 x1 = *(const float2*)(qr1 + d0);
                float2 x2 = *(const float2*)(qr0 + d0 + 8);
                float2 x3 = *(const float2*)(qr1 + d0 + 8);
                bfsplit(x0.x, x0.y, QfH[m][s][0], QfL[m][s][0]);
                bfsplit(x1.x, x1.y, QfH[m][s][1], QfL[m][s][1]);
                bfsplit(x2.x, x2.y, QfH[m][s][2], QfL[m][s][2]);
                bfsplit(x3.x, x3.y, QfH[m][s][3], QfL[m][s][3]);
            }
        }
    }

    float o2[8][4], o1[8][4];
    #pragma unroll
    for (int nt = 0; nt < 8; nt++)
        #pragma unroll
        for (int r = 0; r < 4; r++) { o2[nt][r] = 0.0f; o1[nt][r] = 0.0f; }
    float l2p0 = 0.0f, l2p1 = 0.0f, l1p0 = 0.0f, l1p1 = 0.0f;

    int i0rel = i0 - blo;
    int jloW = i0 - Wn;           if (jloW < blo) jloW = blo;
    int jhiW = i0 + 15 + Wn;      if (jhiW > bhi) jhiW = bhi;
    int jsrel0 = (jloW - blo) & ~1;
    int jendrel = jhiW - blo;
    int m1loR = i0rel - W1, m1hiR = i0rel + 15 + W1;

    for (int js = jsrel0; js <= jendrel; js += 16) {
        float e2[2][4], e1[2][4];
        bool act1[2];
        #pragma unroll
        for (int e = 0; e < 2; e++) {
            int jb = js + 8*e;
            const u32* krH = Kh + (jb + g)*KPL;
            const u32* krL = Kl + (jb + g)*KPL;
            // scores2 (dims 32..63)
            float c[4] = {0.0f, 0.0f, 0.0f, 0.0f};
            #pragma unroll
            for (int s = 0; s < 2; s++) {
                int kp = 16 + 8*s + t;
                u32 bh0 = krH[kp], bh1 = krH[kp + 4];
                u32 bl0 = krL[kp], bl1 = krL[kp + 4];
                mma_bf16(c, QfH[1][s], bh0, bh1);
                mma_bf16(c, QfH[1][s], bl0, bl1);
                mma_bf16(c, QfL[1][s], bh0, bh1);
            }
            int jc0 = jb + 2*t;
            bool v0 = jc0 < nrows, v1 = (jc0 + 1) < nrows;
            float r0 = (float)(jc0 + blo - i0 - g);
            float r1 = r0 + 1.0f;
            float r2 = r0 - 8.0f;
            float r3 = r2 + 1.0f;
            e2[e][0] = v0 ? __expf(c[0]*SCALE + r0*r0*c2) : 0.0f;
            e2[e][1] = v1 ? __expf(c[1]*SCALE + r1*r1*c2) : 0.0f;
            e2[e][2] = v0 ? __expf(c[2]*SCALE + r2*r2*c2) : 0.0f;
            e2[e][3] = v1 ? __expf(c[3]*SCALE + r3*r3*c2) : 0.0f;
            l2p0 += e2[e][0] + e2[e][1];
            l2p1 += e2[e][2] + e2[e][3];
            // scores1 (dims 0..31), gated to the m1 window
            act1[e] = (jb <= m1hiR) && (jb + 7 >= m1loR);
            if (act1[e]) {
                float d[4] = {0.0f, 0.0f, 0.0f, 0.0f};
                #pragma unroll
                for (int s = 0; s < 2; s++) {
                    int kp = 8*s + t;
                    u32 bh0 = krH[kp], bh1 = krH[kp + 4];
                    u32 bl0 = krL[kp], bl1 = krL[kp + 4];
                    mma_bf16(d, QfH[0][s], bh0, bh1);
                    mma_bf16(d, QfH[0][s], bl0, bl1);
                    mma_bf16(d, QfL[0][s], bh0, bh1);
                }
                e1[e][0] = v0 ? __expf(d[0]*SCALE + r0*r0*c1) : 0.0f;
                e1[e][1] = v1 ? __expf(d[1]*SCALE + r1*r1*c1) : 0.0f;
                e1[e][2] = v0 ? __expf(d[2]*SCALE + r2*r2*c1) : 0.0f;
                e1[e][3] = v1 ? __expf(d[3]*SCALE + r3*r3*c1) : 0.0f;
                l1p0 += e1[e][0] + e1[e][1];
                l1p1 += e1[e][2] + e1[e][3];
            } else {
                e1[e][0] = e1[e][1] = e1[e][2] = e1[e][3] = 0.0f;
            }
        }
        // C->A repack: two 8-wide score subtiles = one 16x16 P operand
        u32 p2h[4], p2l[4], p1h[4], p1l[4];
        bfsplit(e2[0][0], e2[0][1], p2h[0], p2l[0]);
        bfsplit(e2[0][2], e2[0][3], p2h[1], p2l[1]);
        bfsplit(e2[1][0], e2[1][1], p2h[2], p2l[2]);
        bfsplit(e2[1][2], e2[1][3], p2h[3], p2l[3]);
        bool anyM1 = act1[0] || act1[1];
        if (anyM1) {
            bfsplit(e1[0][0], e1[0][1], p1h[0], p1l[0]);
            bfsplit(e1[0][2], e1[0][3], p1h[1], p1l[1]);
            bfsplit(e1[1][0], e1[1][1], p1h[2], p1l[2]);
            bfsplit(e1[1][2], e1[1][3], p1h[3], p1l[3]);
        }
        // PV over 8 d-tiles
        int jpb = js >> 1;
        #pragma unroll
        for (int nt = 0; nt < 8; nt++) {
            const u32* vh = Vh + (nt*8 + g)*VLD + jpb;
            const u32* vl = Vl + (nt*8 + g)*VLD + jpb;
            u32 bh0 = vh[t], bh1 = vh[t + 4];
            u32 bl0 = vl[t], bl1 = vl[t + 4];
            mma_bf16(o2[nt], p2h, bh0, bh1);
            mma_bf16(o2[nt], p2l, bh0, bh1);
            mma_bf16(o2[nt], p2h, bl0, bl1);
            if (anyM1) {
                mma_bf16(o1[nt], p1h, bh0, bh1);
                mma_bf16(o1[nt], p1l, bh0, bh1);
                mma_bf16(o1[nt], p1h, bl0, bl1);
            }
        }
    }

    // --- epilogue: normalize, combine, per-head LN(64), scale, store ---
    float L2a = quadsum(l2p0), L2b = quadsum(l2p1);
    float L1a = quadsum(l1p0), L1b = quadsum(l1p1);
    float il1a = 1.0f / L1a, il1b = 1.0f / L1b;
    float il2a = lam / L2a,  il2b = lam / L2b;

    float val[8][4];
    float sA = 0, qA = 0, sB = 0, qB = 0;
    #pragma unroll
    for (int nt = 0; nt < 8; nt++) {
        float v0 = o1[nt][0]*il1a - o2[nt][0]*il2a;
        float v1 = o1[nt][1]*il1a - o2[nt][1]*il2a;
        float v2 = o1[nt][2]*il1b - o2[nt][2]*il2b;
        float v3 = o1[nt][3]*il1b - o2[nt][3]*il2b;
        val[nt][0] = v0; val[nt][1] = v1; val[nt][2] = v2; val[nt][3] = v3;
        sA += v0 + v1;  qA += v0*v0 + v1*v1;
        sB += v2 + v3;  qB += v2*v2 + v3*v3;
    }
    sA = quadsum(sA); qA = quadsum(qA);
    sB = quadsum(sB); qB = quadsum(qB);
    float muA = sA * (1.0f/64.0f);
    float rsA = rsqrtf(qA * (1.0f/64.0f) - muA*muA + LN_EPS);
    float muB = sB * (1.0f/64.0f);
    float rsB = rsqrtf(qB * (1.0f/64.0f) - muB*muB + LN_EPS);
    float post = 1.0f - LAMBDA_INIT;

    float* dstA = g_ho + (size_t)(b*TT + i0 + g)*256 + h*64;
    float* dstB = dstA + (size_t)8*256;
    #pragma unroll
    for (int nt = 0; nt < 8; nt++) {
        int d0 = nt*8 + 2*t;
        float2 w2 = *(const float2*)&hnw[d0];
        float2 b2 = *(const float2*)&hnb[d0];
        float y0 = ((val[nt][0] - muA)*rsA*w2.x + b2.x) * post;
        float y1 = ((val[nt][1] - muA)*rsA*w2.y + b2.y) * post;
        float y2 = ((val[nt][2] - muB)*rsB*w2.x + b2.x) * post;
        float y3 = ((val[nt][3] - muB)*rsB*w2.y + b2.y) * post;
        *(float2*)(dstA + d0) = make_float2(y0, y1);
        *(float2*)(dstB + d0) = make_float2(y2, y3);
    }
}

// ---------------- launch ----------------
extern "C" void kernel_launch(void* const* d_in, const int* in_sizes, int n_in,
                              void* d_out, int out_size) {
    const float* tokens = (const float*)d_in[0];
    const float* ln_w   = (const float*)d_in[1];
    const float* ln_b   = (const float*)d_in[2];
    const float* wq     = (const float*)d_in[3];
    const float* wk     = (const float*)d_in[4];
    const float* wv     = (const float*)d_in[5];
    const float* wo     = (const float*)d_in[6];
    const float* lq1    = (const float*)d_in[7];
    const float* lk1    = (const float*)d_in[8];
    const float* lq2    = (const float*)d_in[9];
    const float* lk2    = (const float*)d_in[10];
    const float* sigS   = (const float*)d_in[11];
    const float* sigN   = (const float*)d_in[12];
    const float* hnw    = (const float*)d_in[13];
    const float* hnb    = (const float*)d_in[14];
    float* out = (float*)d_out;

    cudaFuncSetAttribute(attn_kernel, cudaFuncAttributeMaxDynamicSharedMemorySize, ATTN_SMEM);
    cudaFuncSetAttribute(gemm_qkv, cudaFuncAttributeMaxDynamicSharedMemorySize, GEMM_SMEM);
    cudaFuncSetAttribute(gemm_out, cudaFuncAttributeMaxDynamicSharedMemorySize, GEMM_SMEM);

    ln_stats<<<NTOK/8, 256>>>(tokens);
    gemm_qkv<<<dim3(NTOK/64, 6), 256, GEMM_SMEM>>>(tokens, ln_w, ln_b, wq, wk, wv);
    attn_kernel<<<dim3(TT/QTA, BB*HH), 256, ATTN_SMEM>>>(lq1, lk1, lq2, lk2, sigS, sigN, hnw, hnb);
    gemm_out<<<NTOK/64, 256, GEMM_SMEM>>>(wo, tokens, out);
}

// round 15
// speedup vs baseline: 1.2450x; 1.0616x over previous
#include <cuda_runtime.h>
#include <cuda_fp16.h>
#include <math.h>

// ---------------- problem constants ----------------
#define TT 2048
#define BB 8
#define DD 128
#define HH 4
#define NTOK (BB*TT)          // 16384
#define SCALE 0.17677669529663687f   // 1/sqrt(32)
#define LAMBDA_INIT 0.8f
#define LN_EPS 1e-5f

#define W_MAX 64
#define QTA 128               // queries per attention CTA
#define KRP 272               // padded K band rows (127+2*64+1 = 256, +tile overhang)
#define KPL 36                // K row stride in u32 (banks 4g+t)
#define VLD 140               // V_T row stride in u32 (banks 12g+t, all distinct)
#define JPFILL 136            // V j-pair entries filled

typedef unsigned long long u64;
typedef unsigned int u32;

// ---------------- scratch ----------------
__device__ float g_mu[NTOK];
__device__ float g_rs[NTOK];
__device__ float g_y [NTOK*768];
__device__ float g_ho[NTOK*256];

// ---------------- helpers ----------------
__device__ __forceinline__ float warpsum(float v) {
    #pragma unroll
    for (int o = 16; o; o >>= 1) v += __shfl_xor_sync(0xffffffffu, v, o);
    return v;
}
__device__ __forceinline__ float quadsum(float v) {
    v += __shfl_xor_sync(0xffffffffu, v, 1);
    v += __shfl_xor_sync(0xffffffffu, v, 2);
    return v;
}
// bf16 pack/split (GEMM path, unchanged)
__device__ __forceinline__ u32 bfpack(float upper, float lower) {
    u32 r; asm("cvt.rn.bf16x2.f32 %0, %1, %2;" : "=r"(r) : "f"(upper), "f"(lower));
    return r;
}
__device__ __forceinline__ void bfsplit(float x0, float x1, u32& h, u32& l) {
    h = bfpack(x1, x0);
    float f0 = __uint_as_float(h << 16);
    float f1 = __uint_as_float(h & 0xFFFF0000u);
    l = bfpack(x1 - f1, x0 - f0);
}
__device__ __forceinline__ void mma_bf16(float* c, const u32* a, u32 b0, u32 b1) {
    asm volatile(
        "mma.sync.aligned.m16n8k16.row.col.f32.bf16.bf16.f32 "
        "{%0,%1,%2,%3}, {%4,%5,%6,%7}, {%8,%9}, {%0,%1,%2,%3};"
        : "+f"(c[0]), "+f"(c[1]), "+f"(c[2]), "+f"(c[3])
        : "r"(a[0]), "r"(a[1]), "r"(a[2]), "r"(a[3]), "r"(b0), "r"(b1));
}
// fp16 pack/split (attention path)
__device__ __forceinline__ u32 hfpack(float upper, float lower) {
    u32 r; asm("cvt.rn.f16x2.f32 %0, %1, %2;" : "=r"(r) : "f"(upper), "f"(lower));
    return r;
}
__device__ __forceinline__ void hfsplit(float x0, float x1, u32& h, u32& l) {
    h = hfpack(x1, x0);
    __half2 hv = *reinterpret_cast<__half2*>(&h);
    float f0 = __low2float(hv);
    float f1 = __high2float(hv);
    l = hfpack(x1 - f1, x0 - f0);
}
__device__ __forceinline__ void mma_fp16(float* c, const u32* a, u32 b0, u32 b1) {
    asm volatile(
        "mma.sync.aligned.m16n8k16.row.col.f32.f16.f16.f32 "
        "{%0,%1,%2,%3}, {%4,%5,%6,%7}, {%8,%9}, {%0,%1,%2,%3};"
        : "+f"(c[0]), "+f"(c[1]), "+f"(c[2]), "+f"(c[3])
        : "r"(a[0]), "r"(a[1]), "r"(a[2]), "r"(a[3]), "r"(b0), "r"(b1));
}

// ---------------- stage 1: layernorm stats only ----------------
__global__ void ln_stats(const float* __restrict__ tok) {
    int t = blockIdx.x * 8 + (threadIdx.x >> 5);
    int lane = threadIdx.x & 31;
    const float4* src = (const float4*)(tok + (size_t)t * DD);
    float4 x = src[lane];
    float s  = x.x + x.y + x.z + x.w;
    float sq = x.x*x.x + x.y*x.y + x.z*x.z + x.w*x.w;
    s  = warpsum(s);
    sq = warpsum(sq);
    float mu  = s * (1.0f/128.0f);
    float var = sq * (1.0f/128.0f) - mu*mu;
    if (lane == 0) {
        g_mu[t] = mu;
        g_rs[t] = rsqrtf(var + LN_EPS);
    }
}

// ---------------- 3xBF16 TC GEMM, MT=64 tile, 2-stage double buffer (unchanged R14) ----------------
template<int KTOT, int LDA_G, int LDB_G, bool RESID, bool LNA>
__device__ __forceinline__ void gemm_tc_body(
    const float* __restrict__ Ag,
    const float* __restrict__ Bg,
    float* __restrict__ Cg,
    const float* __restrict__ Rg,
    int ldc,
    const float* __restrict__ mu_p,
    const float* __restrict__ rs_p,
    const float* __restrict__ lnw,
    const float* __restrict__ lnb)
{
    constexpr int MT = 64;
    constexpr int MTILES = 2;
    constexpr int NCHUNK = KTOT / 32;
    constexpr int STAGE_U32 = MT*40 + 16*136*2;
    extern __shared__ __align__(16) float smg[];
    u32* sbase = (u32*)smg;

    int tid = threadIdx.x;
    int lane = tid & 31, wid = tid >> 5;
    int g = lane >> 2, t = lane & 3;
    int warp_m = (wid >> 2) * 32;
    int warp_n = (wid & 3) * 32;

    float acc[MTILES][4][4];
    #pragma unroll
    for (int i = 0; i < MTILES; i++)
        #pragma unroll
        for (int j = 0; j < 4; j++)
            #pragma unroll
            for (int r = 0; r < 4; r++) acc[i][j][r] = 0.0f;

    int a_row = tid >> 2;
    int a_c0  = (tid & 3) * 8;
    int b_kp  = tid >> 4;
    int b_n0  = (tid & 15) * 8;

    float a_mu = 0.0f, a_rs = 1.0f;
    if (LNA) { a_mu = mu_p[a_row]; a_rs = rs_p[a_row]; }

    float4 aReg[2];
    float4 bReg[4];

    auto loadG = [&](int k0) {
        #pragma unroll
        for (int i = 0; i < 2; i++)
            aReg[i] = *(const float4*)&Ag[(size_t)a_row*LDA_G + k0 + a_c0 + i*4];
        const float* B0 = &Bg[(size_t)(k0 + 2*b_kp)*LDB_G + b_n0];
        bReg[0] = *(const float4*)B0;
        bReg[1] = *(const float4*)(B0 + 4);
        bReg[2] = *(const float4*)(B0 + LDB_G);
        bReg[3] = *(const float4*)(B0 + LDB_G + 4);
    };
    auto cvtStore = [&](int s, int k0) {
        u32* AsH = sbase + s*STAGE_U32;
        u32* AsL = AsH + MT*20;
        u32* BsH = AsL + MT*20;
        u32* BsL = BsH + 16*136;
        #pragma unroll
        for (int i = 0; i < 2; i++) {
            int c = a_c0 + i*4;
            float4 a4 = aReg[i];
            if (LNA) {
                float4 w4 = *(const float4*)&lnw[k0 + c];
                float4 b4 = *(const float4*)&lnb[k0 + c];
                a4.x = (a4.x - a_mu) * a_rs * w4.x + b4.x;
                a4.y = (a4.y - a_mu) * a_rs * w4.y + b4.y;
                a4.z = (a4.z - a_mu) * a_rs * w4.z + b4.z;
                a4.w = (a4.w - a_mu) * a_rs * w4.w + b4.w;
            }
            u32 h01, l01, h23, l23;
            bfsplit(a4.x, a4.y, h01, l01);
            bfsplit(a4.z, a4.w, h23, l23);
            int cu = c >> 1;
            *(uint2*)&AsH[a_row*20 + cu] = make_uint2(h01, h23);
            *(uint2*)&AsL[a_row*20 + cu] = make_uint2(l01, l23);
        }
        u32 h[8], l[8];
        bfsplit(bReg[0].x, bReg[2].x, h[0], l[0]);
        bfsplit(bReg[0].y, bReg[2].y, h[1], l[1]);
        bfsplit(bReg[0].z, bReg[2].z, h[2], l[2]);
        bfsplit(bReg[0].w, bReg[2].w, h[3], l[3]);
        bfsplit(bReg[1].x, bReg[3].x, h[4], l[4]);
        bfsplit(bReg[1].y, bReg[3].y, h[5], l[5]);
        bfsplit(bReg[1].z, bReg[3].z, h[6], l[6]);
        bfsplit(bReg[1].w, bReg[3].w, h[7], l[7]);
        u32* dh = &BsH[b_kp*136 + b_n0];
        u32* dl = &BsL[b_kp*136 + b_n0];
        *(uint4*)dh       = make_uint4(h[0], h[1], h[2], h[3]);
        *(uint4*)(dh + 4) = make_uint4(h[4], h[5], h[6], h[7]);
        *(uint4*)dl       = make_uint4(l[0], l[1], l[2], l[3]);
        *(uint4*)(dl + 4) = make_uint4(l[4], l[5], l[6], l[7]);
    };

    loadG(0);
    cvtStore(0, 0);
    __syncthreads();

    for (int c = 0; c < NCHUNK; c++) {
        if (c + 1 < NCHUNK) loadG((c+1)*32);

        u32* AsH = sbase + (c & 1)*STAGE_U32;
        u32* AsL = AsH + MT*20;
        u32* BsH = AsL + MT*20;
        u32* BsL = BsH + 16*136;
        #pragma unroll
        for (int kk = 0; kk < 2; kk++) {
            int kp = kk*8;
            u32 bh[4][2], bl[4][2];
            #pragma unroll
            for (int nt = 0; nt < 4; nt++) {
                int n = warp_n + nt*8 + g;
                bh[nt][0] = BsH[(kp + t)*136 + n];
                bh[nt][1] = BsH[(kp + t + 4)*136 + n];
                bl[nt][0] = BsL[(kp + t)*136 + n];
                bl[nt][1] = BsL[(kp + t + 4)*136 + n];
            }
            #pragma unroll
            for (int mt = 0; mt < MTILES; mt++) {
                int m = warp_m + mt*16;
                u32 ah[4], al[4];
                ah[0] = AsH[(m + g)*20 + kp + t];
                ah[1] = AsH[(m + g + 8)*20 + kp + t];
                ah[2] = AsH[(m + g)*20 + kp + t + 4];
                ah[3] = AsH[(m + g + 8)*20 + kp + t + 4];
                al[0] = AsL[(m + g)*20 + kp + t];
                al[1] = AsL[(m + g + 8)*20 + kp + t];
                al[2] = AsL[(m + g)*20 + kp + t + 4];
                al[3] = AsL[(m + g + 8)*20 + kp + t + 4];
                #pragma unroll
                for (int nt = 0; nt < 4; nt++) {
                    mma_bf16(acc[mt][nt], ah, bh[nt][0], bh[nt][1]);
                    mma_bf16(acc[mt][nt], ah, bl[nt][0], bl[nt][1]);
                    mma_bf16(acc[mt][nt], al, bh[nt][0], bh[nt][1]);
                }
            }
        }
        if (c + 1 < NCHUNK) cvtStore((c+1) & 1, (c+1)*32);
        __syncthreads();
    }

    #pragma unroll
    for (int mt = 0; mt < MTILES; mt++) {
        #pragma unroll
        for (int nt = 0; nt < 4; nt++) {
            int r0 = warp_m + mt*16 + g;
            int col = warp_n + nt*8 + 2*t;
            float* d0 = Cg + (size_t)r0*ldc + col;
            float* d1 = d0 + 8*ldc;
            float c0 = acc[mt][nt][0], c1 = acc[mt][nt][1];
            float c2 = acc[mt][nt][2], c3 = acc[mt][nt][3];
            if (RESID) {
                const float* s0 = Rg + (size_t)r0*ldc + col;
                const float* s1 = s0 + 8*ldc;
                float2 t0 = *(const float2*)s0;
                float2 t1 = *(const float2*)s1;
                c0 += t0.x; c1 += t0.y; c2 += t1.x; c3 += t1.y;
            }
            *(float2*)d0 = make_float2(c0, c1);
            *(float2*)d1 = make_float2(c2, c3);
        }
    }
}

#define GEMM_SMEM ((64*40 + 16*136*2) * 4 * 2)

__global__ void __launch_bounds__(256, 2)
gemm_qkv(const float* __restrict__ tok,
         const float* __restrict__ lnw, const float* __restrict__ lnb,
         const float* __restrict__ wq,
         const float* __restrict__ wk,
         const float* __restrict__ wv) {
    int m0 = blockIdx.x * 64;
    int n0 = blockIdx.y * 128;
    const float* Bsrc; int nb;
    if (n0 < 256)      { Bsrc = wq; nb = n0; }
    else if (n0 < 512) { Bsrc = wk; nb = n0 - 256; }
    else               { Bsrc = wv; nb = n0 - 512; }
    gemm_tc_body<128, 128, 256, false, true>(
        tok + (size_t)m0*128, Bsrc + nb,
        g_y + (size_t)m0*768 + n0, nullptr, 768,
        g_mu + m0, g_rs + m0, lnw, lnb);
}

__global__ void __launch_bounds__(256, 2)
gemm_out(const float* __restrict__ wo,
         const float* __restrict__ tok,
         float* __restrict__ out) {
    int m0 = blockIdx.x * 64;
    gemm_tc_body<256, 256, 128, true, false>(
        g_ho + (size_t)m0*256, wo,
        out + (size_t)m0*128, tok + (size_t)m0*128, 128,
        nullptr, nullptr, nullptr, nullptr);
}

// ---------------- stage 3: fp16 tensor-core banded differential attention ----------------
// Q/K 2-term fp16 (3-mma scores), P 2-term fp16, V 1-term fp16 (2-mma PV).
#define ATTN_SMEM ((2*KRP*KPL + 64*VLD) * 4)

__global__ void __launch_bounds__(256, 1)
attn_kernel(const float* __restrict__ lq1, const float* __restrict__ lk1,
            const float* __restrict__ lq2, const float* __restrict__ lk2,
            const float* __restrict__ sigS, const float* __restrict__ sigN,
            const float* __restrict__ hnw,  const float* __restrict__ hnb) {
    extern __shared__ __align__(16) u32 smu[];
    u32* Kh = smu;                  // [KRP][KPL]
    u32* Kl = Kh + KRP*KPL;
    u32* Vh = Kl + KRP*KPL;         // [64][VLD] d-major, fp16x2 j-pairs
    __shared__ float s_lam;

    int tid = threadIdx.x;
    int bh  = blockIdx.y;
    int b   = bh >> 2;
    int h   = bh & 3;
    int q0  = blockIdx.x * QTA;

    float ss = fmaxf(sigS[0], 1.0f), sn = fmaxf(sigN[0], 1.0f);
    float c1 = -0.5f / (ss*ss);
    float c2 = -0.5f / (sn*sn);
    int Wn = (int)ceilf(6.0f * fmaxf(ss, sn)); if (Wn > W_MAX) Wn = W_MAX;
    int W1 = (int)ceilf(6.0f * ss);            if (W1 > W_MAX) W1 = W_MAX;

    int blo = q0 - Wn;            if (blo < 0) blo = 0;
    int bhi = q0 + QTA - 1 + Wn;  if (bhi > TT-1) bhi = TT-1;
    int nrows = bhi - blo + 1;

    const float* ybase = g_y + (size_t)(b*TT) * 768;

    // --- K band (hi/lo fp16x2 pairs), zero-fill padding rows ---
    for (int idx = tid; idx < KRP*16; idx += 256) {
        int r = idx >> 4, grp = idx & 15;
        u32 h0 = 0, l0 = 0, h1 = 0, l1 = 0;
        if (r < nrows) {
            float4 v4 = *(const float4*)(ybase + (size_t)(blo + r)*768 + h*64 + 256 + grp*4);
            hfsplit(v4.x, v4.y, h0, l0);
            hfsplit(v4.z, v4.w, h1, l1);
        }
        Kh[r*KPL + grp*2]     = h0;
        Kh[r*KPL + grp*2 + 1] = h1;
        Kl[r*KPL + grp*2]     = l0;
        Kl[r*KPL + grp*2 + 1] = l1;
    }
    // --- V transposed (d-major, j-pairs fp16x2, single term) ---
    for (int idx = tid; idx < JPFILL*16; idx += 256) {
        int jp = idx >> 4, dg = idx & 15;
        int r0 = 2*jp, r1 = 2*jp + 1;
        float4 va = make_float4(0,0,0,0), vb = make_float4(0,0,0,0);
        if (r0 < nrows) va = *(const float4*)(ybase + (size_t)(blo + r0)*768 + h*64 + 512 + dg*4);
        if (r1 < nrows) vb = *(const float4*)(ybase + (size_t)(blo + r1)*768 + h*64 + 512 + dg*4);
        Vh[(dg*4+0)*VLD + jp] = hfpack(vb.x, va.x);
        Vh[(dg*4+1)*VLD + jp] = hfpack(vb.y, va.y);
        Vh[(dg*4+2)*VLD + jp] = hfpack(vb.z, va.z);
        Vh[(dg*4+3)*VLD + jp] = hfpack(vb.w, va.w);
    }
    if (tid == 0) {
        float d1 = 0.0f, d2 = 0.0f;
        #pragma unroll
        for (int i = 0; i < 32; i++) { d1 += lq1[i]*lk1[i]; d2 += lq2[i]*lk2[i]; }
        s_lam = __expf(d1) - __expf(d2) + LAMBDA_INIT;
    }
    __syncthreads();
    float lam = s_lam;

    int w = tid >> 5, lane = tid & 31;
    int g = lane >> 2, t = lane & 3;
    int i0 = q0 + w*16;

    // --- Q A-frags in registers (hi/lo fp16, 2 matrices x 2 ksteps) ---
    u32 QfH[2][2][4], QfL[2][2][4];
    {
        const float* qr0 = ybase + (size_t)(i0 + g)*768 + h*64;
        const float* qr1 = qr0 + (size_t)8*768;
        #pragma unroll
        for (int m = 0; m < 2; m++) {
            #pragma unroll
            for (int s = 0; s < 2; s++) {
                int d0 = m*32 + s*16 + 2*t;
                float2 x0 = *(const float2*)(qr0 + d0);
                float2 x1 = *(const float2*)(qr1 + d0);
                float2 x2 = *(const float2*)(qr0 + d0 + 8);
                float2 x3 = *(const float2*)(qr1 + d0 + 8);
                hfsplit(x0.x, x0.y, QfH[m][s][0], QfL[m][s][0]);
                hfsplit(x1.x, x1.y, QfH[m][s][1], QfL[m][s][1]);
                hfsplit(x2.x, x2.y, QfH[m][s][2], QfL[m][s][2]);
                hfsplit(x3.x, x3.y, QfH[m][s][3], QfL[m][s][3]);
            }
        }
    }

    float o2[8][4], o1[8][4];
    #pragma unroll
    for (int nt = 0; nt < 8; nt++)
        #pragma unroll
        for (int r = 0; r < 4; r++) { o2[nt][r] = 0.0f; o1[nt][r] = 0.0f; }
    float l2p0 = 0.0f, l2p1 = 0.0f, l1p0 = 0.0f, l1p1 = 0.0f;

    int i0rel = i0 - blo;
    int jloW = i0 - Wn;           if (jloW < blo) jloW = blo;
    int jhiW = i0 + 15 + Wn;      if (jhiW > bhi) jhiW = bhi;
    int jsrel0 = (jloW - blo) & ~1;
    int jendrel = jhiW - blo;
    int m1loR = i0rel - W1, m1hiR = i0rel + 15 + W1;

    for (int js = jsrel0; js <= jendrel; js += 16) {
        float e2[2][4], e1[2][4];
        bool act1[2];
        #pragma unroll
        for (int e = 0; e < 2; e++) {
            int jb = js + 8*e;
            const u32* krH = Kh + (jb + g)*KPL;
            const u32* krL = Kl + (jb + g)*KPL;
            float c[4] = {0.0f, 0.0f, 0.0f, 0.0f};
            #pragma unroll
            for (int s = 0; s < 2; s++) {
                int kp = 16 + 8*s + t;
                u32 bh0 = krH[kp], bh1 = krH[kp + 4];
                u32 bl0 = krL[kp], bl1 = krL[kp + 4];
                mma_fp16(c, QfH[1][s], bh0, bh1);
                mma_fp16(c, QfH[1][s], bl0, bl1);
                mma_fp16(c, QfL[1][s], bh0, bh1);
            }
            int jc0 = jb + 2*t;
            bool v0 = jc0 < nrows, v1 = (jc0 + 1) < nrows;
            float r0 = (float)(jc0 + blo - i0 - g);
            float r1 = r0 + 1.0f;
            float r2 = r0 - 8.0f;
            float r3 = r2 + 1.0f;
            e2[e][0] = v0 ? __expf(c[0]*SCALE + r0*r0*c2) : 0.0f;
            e2[e][1] = v1 ? __expf(c[1]*SCALE + r1*r1*c2) : 0.0f;
            e2[e][2] = v0 ? __expf(c[2]*SCALE + r2*r2*c2) : 0.0f;
            e2[e][3] = v1 ? __expf(c[3]*SCALE + r3*r3*c2) : 0.0f;
            l2p0 += e2[e][0] + e2[e][1];
            l2p1 += e2[e][2] + e2[e][3];
            act1[e] = (jb <= m1hiR) && (jb + 7 >= m1loR);
            if (act1[e]) {
                float d[4] = {0.0f, 0.0f, 0.0f, 0.0f};
                #pragma unroll
                for (int s = 0; s < 2; s++) {
                    int kp = 8*s + t;
                    u32 bh0 = krH[kp], bh1 = krH[kp + 4];
                    u32 bl0 = krL[kp], bl1 = krL[kp + 4];
                    mma_fp16(d, QfH[0][s], bh0, bh1);
                    mma_fp16(d, QfH[0][s], bl0, bl1);
                    mma_fp16(d, QfL[0][s], bh0, bh1);
                }
                e1[e][0] = v0 ? __expf(d[0]*SCALE + r0*r0*c1) : 0.0f;
                e1[e][1] = v1 ? __expf(d[1]*SCALE + r1*r1*c1) : 0.0f;
                e1[e][2] = v0 ? __expf(d[2]*SCALE + r2*r2*c1) : 0.0f;
                e1[e][3] = v1 ? __expf(d[3]*SCALE + r3*r3*c1) : 0.0f;
                l1p0 += e1[e][0] + e1[e][1];
                l1p1 += e1[e][2] + e1[e][3];
            } else {
                e1[e][0] = e1[e][1] = e1[e][2] = e1[e][3] = 0.0f;
            }
        }
        // C->A repack (2-term fp16 P)
        u32 p2h[4], p2l[4], p1h[4], p1l[4];
        hfsplit(e2[0][0], e2[0][1], p2h[0], p2l[0]);
        hfsplit(e2[0][2], e2[0][3], p2h[1], p2l[1]);
        hfsplit(e2[1][0], e2[1][1], p2h[2], p2l[2]);
        hfsplit(e2[1][2], e2[1][3], p2h[3], p2l[3]);
        bool anyM1 = act1[0] || act1[1];
        if (anyM1) {
            hfsplit(e1[0][0], e1[0][1], p1h[0], p1l[0]);
            hfsplit(e1[0][2], e1[0][3], p1h[1], p1l[1]);
            hfsplit(e1[1][0], e1[1][1], p1h[2], p1l[2]);
            hfsplit(e1[1][2], e1[1][3], p1h[3], p1l[3]);
        }
        // PV: 2-term P x 1-term V
        int jpb = js >> 1;
        #pragma unroll
        for (int nt = 0; nt < 8; nt++) {
            const u32* vh = Vh + (nt*8 + g)*VLD + jpb;
            u32 bh0 = vh[t], bh1 = vh[t + 4];
            mma_fp16(o2[nt], p2h, bh0, bh1);
            mma_fp16(o2[nt], p2l, bh0, bh1);
            if (anyM1) {
                mma_fp16(o1[nt], p1h, bh0, bh1);
                mma_fp16(o1[nt], p1l, bh0, bh1);
            }
        }
    }

    // --- epilogue: normalize, combine, per-head LN(64), scale, store ---
    float L2a = quadsum(l2p0), L2b = quadsum(l2p1);
    float L1a = quadsum(l1p0), L1b = quadsum(l1p1);
    float il1a = 1.0f / L1a, il1b = 1.0f / L1b;
    float il2a = lam / L2a,  il2b = lam / L2b;

    float val[8][4];
    float sA = 0, qA = 0, sB = 0, qB = 0;
    #pragma unroll
    for (int nt = 0; nt < 8; nt++) {
        float v0 = o1[nt][0]*il1a - o2[nt][0]*il2a;
        float v1 = o1[nt][1]*il1a - o2[nt][1]*il2a;
        float v2 = o1[nt][2]*il1b - o2[nt][2]*il2b;
        float v3 = o1[nt][3]*il1b - o2[nt][3]*il2b;
        val[nt][0] = v0; val[nt][1] = v1; val[nt][2] = v2; val[nt][3] = v3;
        sA += v0 + v1;  qA += v0*v0 + v1*v1;
        sB += v2 + v3;  qB += v2*v2 + v3*v3;
    }
    sA = quadsum(sA); qA = quadsum(qA);
    sB = quadsum(sB); qB = quadsum(qB);
    float muA = sA * (1.0f/64.0f);
    float rsA = rsqrtf(qA * (1.0f/64.0f) - muA*muA + LN_EPS);
    float muB = sB * (1.0f/64.0f);
    float rsB = rsqrtf(qB * (1.0f/64.0f) - muB*muB + LN_EPS);
    float post = 1.0f - LAMBDA_INIT;

    float* dstA = g_ho + (size_t)(b*TT + i0 + g)*256 + h*64;
    float* dstB = dstA + (size_t)8*256;
    #pragma unroll
    for (int nt = 0; nt < 8; nt++) {
        int d0 = nt*8 + 2*t;
        float2 w2 = *(const float2*)&hnw[d0];
        float2 b2 = *(const float2*)&hnb[d0];
        float y0 = ((val[nt][0] - muA)*rsA*w2.x + b2.x) * post;
        float y1 = ((val[nt][1] - muA)*rsA*w2.y + b2.y) * post;
        float y2 = ((val[nt][2] - muB)*rsB*w2.x + b2.x) * post;
        float y3 = ((val[nt][3] - muB)*rsB*w2.y + b2.y) * post;
        *(float2*)(dstA + d0) = make_float2(y0, y1);
        *(float2*)(dstB + d0) = make_float2(y2, y3);
    }
}

// ---------------- launch ----------------
extern "C" void kernel_launch(void* const* d_in, const int* in_sizes, int n_in,
                              void* d_out, int out_size) {
    const float* tokens = (const float*)d_in[0];
    const float* ln_w   = (const float*)d_in[1];
    const float* ln_b   = (const float*)d_in[2];
    const float* wq     = (const float*)d_in[3];
    const float* wk     = (const float*)d_in[4];
    const float* wv     = (const float*)d_in[5];
    const float* wo     = (const float*)d_in[6];
    const float* lq1    = (const float*)d_in[7];
    const float* lk1    = (const float*)d_in[8];
    const float* lq2    = (const float*)d_in[9];
    const float* lk2    = (const float*)d_in[10];
    const float* sigS   = (const float*)d_in[11];
    const float* sigN   = (const float*)d_in[12];
    const float* hnw    = (const float*)d_in[13];
    const float* hnb    = (const float*)d_in[14];
    float* out = (float*)d_out;

    cudaFuncSetAttribute(attn_kernel, cudaFuncAttributeMaxDynamicSharedMemorySize, ATTN_SMEM);
    cudaFuncSetAttribute(gemm_qkv, cudaFuncAttributeMaxDynamicSharedMemorySize, GEMM_SMEM);
    cudaFuncSetAttribute(gemm_out, cudaFuncAttributeMaxDynamicSharedMemorySize, GEMM_SMEM);

    ln_stats<<<NTOK/8, 256>>>(tokens);
    gemm_qkv<<<dim3(NTOK/64, 6), 256, GEMM_SMEM>>>(tokens, ln_w, ln_b, wq, wk, wv);
    attn_kernel<<<dim3(TT/QTA, BB*HH), 256, ATTN_SMEM>>>(lq1, lk1, lq2, lk2, sigS, sigN, hnw, hnb);
    gemm_out<<<NTOK/64, 256, GEMM_SMEM>>>(wo, tokens, out);
}

// round 16
// speedup vs baseline: 1.5343x; 1.2324x over previous
#include <cuda_runtime.h>
#include <cuda_fp16.h>
#include <math.h>

// ---------------- problem constants ----------------
#define TT 2048
#define BB 8
#define DD 128
#define HH 4
#define NTOK (BB*TT)          // 16384
#define SCALE 0.17677669529663687f   // 1/sqrt(32)
#define LAMBDA_INIT 0.8f
#define LN_EPS 1e-5f

#define W_MAX 64
#define QTA 128               // queries per attention CTA
#define KRP 272               // padded K band rows
#define KPL 36                // K row stride in u32
#define VLD 140               // V_T row stride in u32
#define JPFILL 136            // V j-pair entries filled

typedef unsigned long long u64;
typedef unsigned int u32;

// ---------------- scratch ----------------
__device__ float g_mu[NTOK];
__device__ float g_rs[NTOK];
__device__ float g_y [NTOK*768];
__device__ float g_ho[NTOK*256];

// ---------------- helpers ----------------
__device__ __forceinline__ float warpsum(float v) {
    #pragma unroll
    for (int o = 16; o; o >>= 1) v += __shfl_xor_sync(0xffffffffu, v, o);
    return v;
}
__device__ __forceinline__ float quadsum(float v) {
    v += __shfl_xor_sync(0xffffffffu, v, 1);
    v += __shfl_xor_sync(0xffffffffu, v, 2);
    return v;
}
// bf16 pack/split (GEMM path)
__device__ __forceinline__ u32 bfpack(float upper, float lower) {
    u32 r; asm("cvt.rn.bf16x2.f32 %0, %1, %2;" : "=r"(r) : "f"(upper), "f"(lower));
    return r;
}
__device__ __forceinline__ void bfsplit(float x0, float x1, u32& h, u32& l) {
    h = bfpack(x1, x0);
    float f0 = __uint_as_float(h << 16);
    float f1 = __uint_as_float(h & 0xFFFF0000u);
    l = bfpack(x1 - f1, x0 - f0);
}
__device__ __forceinline__ void mma_bf16(float* c, const u32* a, u32 b0, u32 b1) {
    asm volatile(
        "mma.sync.aligned.m16n8k16.row.col.f32.bf16.bf16.f32 "
        "{%0,%1,%2,%3}, {%4,%5,%6,%7}, {%8,%9}, {%0,%1,%2,%3};"
        : "+f"(c[0]), "+f"(c[1]), "+f"(c[2]), "+f"(c[3])
        : "r"(a[0]), "r"(a[1]), "r"(a[2]), "r"(a[3]), "r"(b0), "r"(b1));
}
// fp16 pack/split (attention path)
__device__ __forceinline__ u32 hfpack(float upper, float lower) {
    u32 r; asm("cvt.rn.f16x2.f32 %0, %1, %2;" : "=r"(r) : "f"(upper), "f"(lower));
    return r;
}
__device__ __forceinline__ void hfsplit(float x0, float x1, u32& h, u32& l) {
    h = hfpack(x1, x0);
    __half2 hv = *reinterpret_cast<__half2*>(&h);
    float f0 = __low2float(hv);
    float f1 = __high2float(hv);
    l = hfpack(x1 - f1, x0 - f0);
}
__device__ __forceinline__ void mma_fp16(float* c, const u32* a, u32 b0, u32 b1) {
    asm volatile(
        "mma.sync.aligned.m16n8k16.row.col.f32.f16.f16.f32 "
        "{%0,%1,%2,%3}, {%4,%5,%6,%7}, {%8,%9}, {%0,%1,%2,%3};"
        : "+f"(c[0]), "+f"(c[1]), "+f"(c[2]), "+f"(c[3])
        : "r"(a[0]), "r"(a[1]), "r"(a[2]), "r"(a[3]), "r"(b0), "r"(b1));
}

// ---------------- stage 1: layernorm stats only ----------------
__global__ void ln_stats(const float* __restrict__ tok) {
    int t = blockIdx.x * 8 + (threadIdx.x >> 5);
    int lane = threadIdx.x & 31;
    const float4* src = (const float4*)(tok + (size_t)t * DD);
    float4 x = src[lane];
    float s  = x.x + x.y + x.z + x.w;
    float sq = x.x*x.x + x.y*x.y + x.z*x.z + x.w*x.w;
    s  = warpsum(s);
    sq = warpsum(sq);
    float mu  = s * (1.0f/128.0f);
    float var = sq * (1.0f/128.0f) - mu*mu;
    if (lane == 0) {
        g_mu[t] = mu;
        g_rs[t] = rsqrtf(var + LN_EPS);
    }
}

// ---------------- 3xBF16 TC GEMM, MT=64 tile, 2-stage double buffer ----------------
template<int KTOT, int LDA_G, int LDB_G, bool RESID, bool LNA>
__device__ __forceinline__ void gemm_tc_body(
    const float* __restrict__ Ag,
    const float* __restrict__ Bg,
    float* __restrict__ Cg,
    const float* __restrict__ Rg,
    int ldc,
    const float* __restrict__ mu_p,
    const float* __restrict__ rs_p,
    const float* __restrict__ lnw,
    const float* __restrict__ lnb)
{
    constexpr int MT = 64;
    constexpr int MTILES = 2;
    constexpr int NCHUNK = KTOT / 32;
    constexpr int STAGE_U32 = MT*40 + 16*136*2;
    extern __shared__ __align__(16) float smg[];
    u32* sbase = (u32*)smg;

    int tid = threadIdx.x;
    int lane = tid & 31, wid = tid >> 5;
    int g = lane >> 2, t = lane & 3;
    int warp_m = (wid >> 2) * 32;
    int warp_n = (wid & 3) * 32;

    float acc[MTILES][4][4];
    #pragma unroll
    for (int i = 0; i < MTILES; i++)
        #pragma unroll
        for (int j = 0; j < 4; j++)
            #pragma unroll
            for (int r = 0; r < 4; r++) acc[i][j][r] = 0.0f;

    int a_row = tid >> 2;
    int a_c0  = (tid & 3) * 8;
    int b_kp  = tid >> 4;
    int b_n0  = (tid & 15) * 8;

    float a_mu = 0.0f, a_rs = 1.0f;
    if (LNA) { a_mu = mu_p[a_row]; a_rs = rs_p[a_row]; }

    float4 aReg[2];
    float4 bReg[4];

    auto loadG = [&](int k0) {
        #pragma unroll
        for (int i = 0; i < 2; i++)
            aReg[i] = *(const float4*)&Ag[(size_t)a_row*LDA_G + k0 + a_c0 + i*4];
        const float* B0 = &Bg[(size_t)(k0 + 2*b_kp)*LDB_G + b_n0];
        bReg[0] = *(const float4*)B0;
        bReg[1] = *(const float4*)(B0 + 4);
        bReg[2] = *(const float4*)(B0 + LDB_G);
        bReg[3] = *(const float4*)(B0 + LDB_G + 4);
    };
    auto cvtStore = [&](int s, int k0) {
        u32* AsH = sbase + s*STAGE_U32;
        u32* AsL = AsH + MT*20;
        u32* BsH = AsL + MT*20;
        u32* BsL = BsH + 16*136;
        #pragma unroll
        for (int i = 0; i < 2; i++) {
            int c = a_c0 + i*4;
            float4 a4 = aReg[i];
            if (LNA) {
                float4 w4 = *(const float4*)&lnw[k0 + c];
                float4 b4 = *(const float4*)&lnb[k0 + c];
                a4.x = (a4.x - a_mu) * a_rs * w4.x + b4.x;
                a4.y = (a4.y - a_mu) * a_rs * w4.y + b4.y;
                a4.z = (a4.z - a_mu) * a_rs * w4.z + b4.z;
                a4.w = (a4.w - a_mu) * a_rs * w4.w + b4.w;
            }
            u32 h01, l01, h23, l23;
            bfsplit(a4.x, a4.y, h01, l01);
            bfsplit(a4.z, a4.w, h23, l23);
            int cu = c >> 1;
            *(uint2*)&AsH[a_row*20 + cu] = make_uint2(h01, h23);
            *(uint2*)&AsL[a_row*20 + cu] = make_uint2(l01, l23);
        }
        u32 h[8], l[8];
        bfsplit(bReg[0].x, bReg[2].x, h[0], l[0]);
        bfsplit(bReg[0].y, bReg[2].y, h[1], l[1]);
        bfsplit(bReg[0].z, bReg[2].z, h[2], l[2]);
        bfsplit(bReg[0].w, bReg[2].w, h[3], l[3]);
        bfsplit(bReg[1].x, bReg[3].x, h[4], l[4]);
        bfsplit(bReg[1].y, bReg[3].y, h[5], l[5]);
        bfsplit(bReg[1].z, bReg[3].z, h[6], l[6]);
        bfsplit(bReg[1].w, bReg[3].w, h[7], l[7]);
        u32* dh = &BsH[b_kp*136 + b_n0];
        u32* dl = &BsL[b_kp*136 + b_n0];
        *(uint4*)dh       = make_uint4(h[0], h[1], h[2], h[3]);
        *(uint4*)(dh + 4) = make_uint4(h[4], h[5], h[6], h[7]);
        *(uint4*)dl       = make_uint4(l[0], l[1], l[2], l[3]);
        *(uint4*)(dl + 4) = make_uint4(l[4], l[5], l[6], l[7]);
    };

    loadG(0);
    cvtStore(0, 0);
    __syncthreads();

    for (int c = 0; c < NCHUNK; c++) {
        if (c + 1 < NCHUNK) loadG((c+1)*32);

        u32* AsH = sbase + (c & 1)*STAGE_U32;
        u32* AsL = AsH + MT*20;
        u32* BsH = AsL + MT*20;
        u32* BsL = BsH + 16*136;
        #pragma unroll
        for (int kk = 0; kk < 2; kk++) {
            int kp = kk*8;
            u32 bh[4][2], bl[4][2];
            #pragma unroll
            for (int nt = 0; nt < 4; nt++) {
                int n = warp_n + nt*8 + g;
                bh[nt][0] = BsH[(kp + t)*136 + n];
                bh[nt][1] = BsH[(kp + t + 4)*136 + n];
                bl[nt][0] = BsL[(kp + t)*136 + n];
                bl[nt][1] = BsL[(kp + t + 4)*136 + n];
            }
            #pragma unroll
            for (int mt = 0; mt < MTILES; mt++) {
                int m = warp_m + mt*16;
                u32 ah[4], al[4];
                ah[0] = AsH[(m + g)*20 + kp + t];
                ah[1] = AsH[(m + g + 8)*20 + kp + t];
                ah[2] = AsH[(m + g)*20 + kp + t + 4];
                ah[3] = AsH[(m + g + 8)*20 + kp + t + 4];
                al[0] = AsL[(m + g)*20 + kp + t];
                al[1] = AsL[(m + g + 8)*20 + kp + t];
                al[2] = AsL[(m + g)*20 + kp + t + 4];
                al[3] = AsL[(m + g + 8)*20 + kp + t + 4];
                #pragma unroll
                for (int nt = 0; nt < 4; nt++) {
                    mma_bf16(acc[mt][nt], ah, bh[nt][0], bh[nt][1]);
                    mma_bf16(acc[mt][nt], ah, bl[nt][0], bl[nt][1]);
                    mma_bf16(acc[mt][nt], al, bh[nt][0], bh[nt][1]);
                }
            }
        }
        if (c + 1 < NCHUNK) cvtStore((c+1) & 1, (c+1)*32);
        __syncthreads();
    }

    #pragma unroll
    for (int mt = 0; mt < MTILES; mt++) {
        #pragma unroll
        for (int nt = 0; nt < 4; nt++) {
            int r0 = warp_m + mt*16 + g;
            int col = warp_n + nt*8 + 2*t;
            float* d0 = Cg + (size_t)r0*ldc + col;
            float* d1 = d0 + 8*ldc;
            float c0 = acc[mt][nt][0], c1 = acc[mt][nt][1];
            float c2 = acc[mt][nt][2], c3 = acc[mt][nt][3];
            if (RESID) {
                const float* s0 = Rg + (size_t)r0*ldc + col;
                const float* s1 = s0 + 8*ldc;
                float2 t0 = *(const float2*)s0;
                float2 t1 = *(const float2*)s1;
                c0 += t0.x; c1 += t0.y; c2 += t1.x; c3 += t1.y;
            }
            *(float2*)d0 = make_float2(c0, c1);
            *(float2*)d1 = make_float2(c2, c3);
        }
    }
}

#define GEMM_SMEM ((64*40 + 16*136*2) * 4 * 2)

__global__ void __launch_bounds__(256, 2)
gemm_qkv(const float* __restrict__ tok,
         const float* __restrict__ lnw, const float* __restrict__ lnb,
         const float* __restrict__ wq,
         const float* __restrict__ wk,
         const float* __restrict__ wv) {
    int m0 = blockIdx.x * 64;
    int n0 = blockIdx.y * 128;
    const float* Bsrc; int nb;
    if (n0 < 256)      { Bsrc = wq; nb = n0; }
    else if (n0 < 512) { Bsrc = wk; nb = n0 - 256; }
    else               { Bsrc = wv; nb = n0 - 512; }
    gemm_tc_body<128, 128, 256, false, true>(
        tok + (size_t)m0*128, Bsrc + nb,
        g_y + (size_t)m0*768 + n0, nullptr, 768,
        g_mu + m0, g_rs + m0, lnw, lnb);
}

__global__ void __launch_bounds__(256, 2)
gemm_out(const float* __restrict__ wo,
         const float* __restrict__ tok,
         float* __restrict__ out) {
    int m0 = blockIdx.x * 64;
    gemm_tc_body<256, 256, 128, true, false>(
        g_ho + (size_t)m0*256, wo,
        out + (size_t)m0*128, tok + (size_t)m0*128, 128,
        nullptr, nullptr, nullptr, nullptr);
}

// ---------------- stage 3: fp16 tensor-core banded differential attention ----------------
// Q 1-term fp16 (hi), K 2-term (scores = Qh*(Kh+Kl), 2 mma), P 2-term, V 1-term.
// 2 CTAs/SM (smem 111.5 KB x2 fits the 228 KB carveout).
#define ATTN_SMEM ((2*KRP*KPL + 64*VLD) * 4)

__global__ void __launch_bounds__(256, 2)
attn_kernel(const float* __restrict__ lq1, const float* __restrict__ lk1,
            const float* __restrict__ lq2, const float* __restrict__ lk2,
            const float* __restrict__ sigS, const float* __restrict__ sigN,
            const float* __restrict__ hnw,  const float* __restrict__ hnb) {
    extern __shared__ __align__(16) u32 smu[];
    u32* Kh = smu;                  // [KRP][KPL]
    u32* Kl = Kh + KRP*KPL;
    u32* Vh = Kl + KRP*KPL;         // [64][VLD] d-major, fp16x2 j-pairs
    __shared__ float s_lam;

    int tid = threadIdx.x;
    int bh  = blockIdx.y;
    int b   = bh >> 2;
    int h   = bh & 3;
    int q0  = blockIdx.x * QTA;

    float ss = fmaxf(sigS[0], 1.0f), sn = fmaxf(sigN[0], 1.0f);
    float c1 = -0.5f / (ss*ss);
    float c2 = -0.5f / (sn*sn);
    int Wn = (int)ceilf(6.0f * fmaxf(ss, sn)); if (Wn > W_MAX) Wn = W_MAX;
    int W1 = (int)ceilf(6.0f * ss);            if (W1 > W_MAX) W1 = W_MAX;

    int blo = q0 - Wn;            if (blo < 0) blo = 0;
    int bhi = q0 + QTA - 1 + Wn;  if (bhi > TT-1) bhi = TT-1;
    int nrows = bhi - blo + 1;

    const float* ybase = g_y + (size_t)(b*TT) * 768;

    // --- K band (hi/lo fp16x2 pairs), zero-fill padding rows ---
    for (int idx = tid; idx < KRP*16; idx += 256) {
        int r = idx >> 4, grp = idx & 15;
        u32 h0 = 0, l0 = 0, h1 = 0, l1 = 0;
        if (r < nrows) {
            float4 v4 = *(const float4*)(ybase + (size_t)(blo + r)*768 + h*64 + 256 + grp*4);
            hfsplit(v4.x, v4.y, h0, l0);
            hfsplit(v4.z, v4.w, h1, l1);
        }
        Kh[r*KPL + grp*2]     = h0;
        Kh[r*KPL + grp*2 + 1] = h1;
        Kl[r*KPL + grp*2]     = l0;
        Kl[r*KPL + grp*2 + 1] = l1;
    }
    // --- V transposed (d-major, j-pairs fp16x2, single term) ---
    for (int idx = tid; idx < JPFILL*16; idx += 256) {
        int jp = idx >> 4, dg = idx & 15;
        int r0 = 2*jp, r1 = 2*jp + 1;
        float4 va = make_float4(0,0,0,0), vb = make_float4(0,0,0,0);
        if (r0 < nrows) va = *(const float4*)(ybase + (size_t)(blo + r0)*768 + h*64 + 512 + dg*4);
        if (r1 < nrows) vb = *(const float4*)(ybase + (size_t)(blo + r1)*768 + h*64 + 512 + dg*4);
        Vh[(dg*4+0)*VLD + jp] = hfpack(vb.x, va.x);
        Vh[(dg*4+1)*VLD + jp] = hfpack(vb.y, va.y);
        Vh[(dg*4+2)*VLD + jp] = hfpack(vb.z, va.z);
        Vh[(dg*4+3)*VLD + jp] = hfpack(vb.w, va.w);
    }
    if (tid == 0) {
        float d1 = 0.0f, d2 = 0.0f;
        #pragma unroll
        for (int i = 0; i < 32; i++) { d1 += lq1[i]*lk1[i]; d2 += lq2[i]*lk2[i]; }
        s_lam = __expf(d1) - __expf(d2) + LAMBDA_INIT;
    }
    __syncthreads();
    float lam = s_lam;

    int w = tid >> 5, lane = tid & 31;
    int g = lane >> 2, t = lane & 3;
    int i0 = q0 + w*16;

    // --- Q A-frags in registers (hi only, 2 matrices x 2 ksteps) ---
    u32 Qf[2][2][4];
    {
        const float* qr0 = ybase + (size_t)(i0 + g)*768 + h*64;
        const float* qr1 = qr0 + (size_t)8*768;
        #pragma unroll
        for (int m = 0; m < 2; m++) {
            #pragma unroll
            for (int s = 0; s < 2; s++) {
                int d0 = m*32 + s*16 + 2*t;
                float2 x0 = *(const float2*)(qr0 + d0);
                float2 x1 = *(const float2*)(qr1 + d0);
                float2 x2 = *(const float2*)(qr0 + d0 + 8);
                float2 x3 = *(const float2*)(qr1 + d0 + 8);
                Qf[m][s][0] = hfpack(x0.y, x0.x);
                Qf[m][s][1] = hfpack(x1.y, x1.x);
                Qf[m][s][2] = hfpack(x2.y, x2.x);
                Qf[m][s][3] = hfpack(x3.y, x3.x);
            }
        }
    }

    float o2[8][4], o1[8][4];
    #pragma unroll
    for (int nt = 0; nt < 8; nt++)
        #pragma unroll
        for (int r = 0; r < 4; r++) { o2[nt][r] = 0.0f; o1[nt][r] = 0.0f; }
    float l2p0 = 0.0f, l2p1 = 0.0f, l1p0 = 0.0f, l1p1 = 0.0f;

    int i0rel = i0 - blo;
    int jloW = i0 - Wn;           if (jloW < blo) jloW = blo;
    int jhiW = i0 + 15 + Wn;      if (jhiW > bhi) jhiW = bhi;
    int jsrel0 = (jloW - blo) & ~1;
    int jendrel = jhiW - blo;
    int m1loR = i0rel - W1, m1hiR = i0rel + 15 + W1;

    for (int js = jsrel0; js <= jendrel; js += 16) {
        float e2[2][4], e1[2][4];
        bool act1[2];
        #pragma unroll
        for (int e = 0; e < 2; e++) {
            int jb = js + 8*e;
            const u32* krH = Kh + (jb + g)*KPL;
            const u32* krL = Kl + (jb + g)*KPL;
            float c[4] = {0.0f, 0.0f, 0.0f, 0.0f};
            #pragma unroll
            for (int s = 0; s < 2; s++) {
                int kp = 16 + 8*s + t;
                u32 bh0 = krH[kp], bh1 = krH[kp + 4];
                u32 bl0 = krL[kp], bl1 = krL[kp + 4];
                mma_fp16(c, Qf[1][s], bh0, bh1);
                mma_fp16(c, Qf[1][s], bl0, bl1);
            }
            int jc0 = jb + 2*t;
            bool v0 = jc0 < nrows, v1 = (jc0 + 1) < nrows;
            float r0 = (float)(jc0 + blo - i0 - g);
            float r1 = r0 + 1.0f;
            float r2 = r0 - 8.0f;
            float r3 = r2 + 1.0f;
            e2[e][0] = v0 ? __expf(c[0]*SCALE + r0*r0*c2) : 0.0f;
            e2[e][1] = v1 ? __expf(c[1]*SCALE + r1*r1*c2) : 0.0f;
            e2[e][2] = v0 ? __expf(c[2]*SCALE + r2*r2*c2) : 0.0f;
            e2[e][3] = v1 ? __expf(c[3]*SCALE + r3*r3*c2) : 0.0f;
            l2p0 += e2[e][0] + e2[e][1];
            l2p1 += e2[e][2] + e2[e][3];
            act1[e] = (jb <= m1hiR) && (jb + 7 >= m1loR);
            if (act1[e]) {
                float d[4] = {0.0f, 0.0f, 0.0f, 0.0f};
                #pragma unroll
                for (int s = 0; s < 2; s++) {
                    int kp = 8*s + t;
                    u32 bh0 = krH[kp], bh1 = krH[kp + 4];
                    u32 bl0 = krL[kp], bl1 = krL[kp + 4];
                    mma_fp16(d, Qf[0][s], bh0, bh1);
                    mma_fp16(d, Qf[0][s], bl0, bl1);
                }
                e1[e][0] = v0 ? __expf(d[0]*SCALE + r0*r0*c1) : 0.0f;
                e1[e][1] = v1 ? __expf(d[1]*SCALE + r1*r1*c1) : 0.0f;
                e1[e][2] = v0 ? __expf(d[2]*SCALE + r2*r2*c1) : 0.0f;
                e1[e][3] = v1 ? __expf(d[3]*SCALE + r3*r3*c1) : 0.0f;
                l1p0 += e1[e][0] + e1[e][1];
                l1p1 += e1[e][2] + e1[e][3];
            } else {
                e1[e][0] = e1[e][1] = e1[e][2] = e1[e][3] = 0.0f;
            }
        }
        // C->A repack (2-term fp16 P)
        u32 p2h[4], p2l[4], p1h[4], p1l[4];
        hfsplit(e2[0][0], e2[0][1], p2h[0], p2l[0]);
        hfsplit(e2[0][2], e2[0][3], p2h[1], p2l[1]);
        hfsplit(e2[1][0], e2[1][1], p2h[2], p2l[2]);
        hfsplit(e2[1][2], e2[1][3], p2h[3], p2l[3]);
        bool anyM1 = act1[0] || act1[1];
        if (anyM1) {
            hfsplit(e1[0][0], e1[0][1], p1h[0], p1l[0]);
            hfsplit(e1[0][2], e1[0][3], p1h[1], p1l[1]);
            hfsplit(e1[1][0], e1[1][1], p1h[2], p1l[2]);
            hfsplit(e1[1][2], e1[1][3], p1h[3], p1l[3]);
        }
        // PV: 2-term P x 1-term V
        int jpb = js >> 1;
        #pragma unroll
        for (int nt = 0; nt < 8; nt++) {
            const u32* vh = Vh + (nt*8 + g)*VLD + jpb;
            u32 bh0 = vh[t], bh1 = vh[t + 4];
            mma_fp16(o2[nt], p2h, bh0, bh1);
            mma_fp16(o2[nt], p2l, bh0, bh1);
            if (anyM1) {
                mma_fp16(o1[nt], p1h, bh0, bh1);
                mma_fp16(o1[nt], p1l, bh0, bh1);
            }
        }
    }

    // --- epilogue: normalize, combine, per-head LN(64), scale, store ---
    float L2a = quadsum(l2p0), L2b = quadsum(l2p1);
    float L1a = quadsum(l1p0), L1b = quadsum(l1p1);
    float il1a = 1.0f / L1a, il1b = 1.0f / L1b;
    float il2a = lam / L2a,  il2b = lam / L2b;

    float val[8][4];
    float sA = 0, qA = 0, sB = 0, qB = 0;
    #pragma unroll
    for (int nt = 0; nt < 8; nt++) {
        float v0 = o1[nt][0]*il1a - o2[nt][0]*il2a;
        float v1 = o1[nt][1]*il1a - o2[nt][1]*il2a;
        float v2 = o1[nt][2]*il1b - o2[nt][2]*il2b;
        float v3 = o1[nt][3]*il1b - o2[nt][3]*il2b;
        val[nt][0] = v0; val[nt][1] = v1; val[nt][2] = v2; val[nt][3] = v3;
        sA += v0 + v1;  qA += v0*v0 + v1*v1;
        sB += v2 + v3;  qB += v2*v2 + v3*v3;
    }
    sA = quadsum(sA); qA = quadsum(qA);
    sB = quadsum(sB); qB = quadsum(qB);
    float muA = sA * (1.0f/64.0f);
    float rsA = rsqrtf(qA * (1.0f/64.0f) - muA*muA + LN_EPS);
    float muB = sB * (1.0f/64.0f);
    float rsB = rsqrtf(qB * (1.0f/64.0f) - muB*muB + LN_EPS);
    float post = 1.0f - LAMBDA_INIT;

    float* dstA = g_ho + (size_t)(b*TT + i0 + g)*256 + h*64;
    float* dstB = dstA + (size_t)8*256;
    #pragma unroll
    for (int nt = 0; nt < 8; nt++) {
        int d0 = nt*8 + 2*t;
        float2 w2 = *(const float2*)&hnw[d0];
        float2 b2 = *(const float2*)&hnb[d0];
        float y0 = ((val[nt][0] - muA)*rsA*w2.x + b2.x) * post;
        float y1 = ((val[nt][1] - muA)*rsA*w2.y + b2.y) * post;
        float y2 = ((val[nt][2] - muB)*rsB*w2.x + b2.x) * post;
        float y3 = ((val[nt][3] - muB)*rsB*w2.y + b2.y) * post;
        *(float2*)(dstA + d0) = make_float2(y0, y1);
        *(float2*)(dstB + d0) = make_float2(y2, y3);
    }
}

// ---------------- launch ----------------
extern "C" void kernel_launch(void* const* d_in, const int* in_sizes, int n_in,
                              void* d_out, int out_size) {
    const float* tokens = (const float*)d_in[0];
    const float* ln_w   = (const float*)d_in[1];
    const float* ln_b   = (const float*)d_in[2];
    const float* wq     = (const float*)d_in[3];
    const float* wk     = (const float*)d_in[4];
    const float* wv     = (const float*)d_in[5];
    const float* wo     = (const float*)d_in[6];
    const float* lq1    = (const float*)d_in[7];
    const float* lk1    = (const float*)d_in[8];
    const float* lq2    = (const float*)d_in[9];
    const float* lk2    = (const float*)d_in[10];
    const float* sigS   = (const float*)d_in[11];
    const float* sigN   = (const float*)d_in[12];
    const float* hnw    = (const float*)d_in[13];
    const float* hnb    = (const float*)d_in[14];
    float* out = (float*)d_out;

    cudaFuncSetAttribute(attn_kernel, cudaFuncAttributeMaxDynamicSharedMemorySize, ATTN_SMEM);
    cudaFuncSetAttribute(gemm_qkv, cudaFuncAttributeMaxDynamicSharedMemorySize, GEMM_SMEM);
    cudaFuncSetAttribute(gemm_out, cudaFuncAttributeMaxDynamicSharedMemorySize, GEMM_SMEM);

    ln_stats<<<NTOK/8, 256>>>(tokens);
    gemm_qkv<<<dim3(NTOK/64, 6), 256, GEMM_SMEM>>>(tokens, ln_w, ln_b, wq, wk, wv);
    attn_kernel<<<dim3(TT/QTA, BB*HH), 256, ATTN_SMEM>>>(lq1, lk1, lq2, lk2, sigS, sigN, hnw, hnb);
    gemm_out<<<NTOK/64, 256, GEMM_SMEM>>>(wo, tokens, out);
}

// round 17
// speedup vs baseline: 1.6773x; 1.0932x over previous
#include <cuda_runtime.h>
#include <cuda_fp16.h>
#include <math.h>

// ---------------- problem constants ----------------
#define TT 2048
#define BB 8
#define DD 128
#define HH 4
#define NTOK (BB*TT)          // 16384
#define SCALE 0.17677669529663687f   // 1/sqrt(32)
#define LAMBDA_INIT 0.8f
#define LN_EPS 1e-5f

#define W_MAX 64
#define QTA 128               // queries per attention CTA
#define KRP 272               // padded K band rows
#define KPL 36                // K row stride in u32 (32 + pad)
#define VLD 140               // V_T row stride in u32
#define JPFILL 136            // V j-pair entries filled

typedef unsigned long long u64;
typedef unsigned int u32;

// ---------------- scratch ----------------
__device__ float  g_mu[NTOK];
__device__ float  g_rs[NTOK];
__device__ __half g_y [NTOK*768];     // qkv projections, fp16 (12 MB)
__device__ float  g_ho[NTOK*256];

// ---------------- helpers ----------------
__device__ __forceinline__ float warpsum(float v) {
    #pragma unroll
    for (int o = 16; o; o >>= 1) v += __shfl_xor_sync(0xffffffffu, v, o);
    return v;
}
__device__ __forceinline__ float quadsum(float v) {
    v += __shfl_xor_sync(0xffffffffu, v, 1);
    v += __shfl_xor_sync(0xffffffffu, v, 2);
    return v;
}
// bf16 pack/split (gemm_out path)
__device__ __forceinline__ u32 bfpack(float upper, float lower) {
    u32 r; asm("cvt.rn.bf16x2.f32 %0, %1, %2;" : "=r"(r) : "f"(upper), "f"(lower));
    return r;
}
__device__ __forceinline__ void bfsplit(float x0, float x1, u32& h, u32& l) {
    h = bfpack(x1, x0);
    float f0 = __uint_as_float(h << 16);
    float f1 = __uint_as_float(h & 0xFFFF0000u);
    l = bfpack(x1 - f1, x0 - f0);
}
__device__ __forceinline__ void mma_bf16(float* c, const u32* a, u32 b0, u32 b1) {
    asm volatile(
        "mma.sync.aligned.m16n8k16.row.col.f32.bf16.bf16.f32 "
        "{%0,%1,%2,%3}, {%4,%5,%6,%7}, {%8,%9}, {%0,%1,%2,%3};"
        : "+f"(c[0]), "+f"(c[1]), "+f"(c[2]), "+f"(c[3])
        : "r"(a[0]), "r"(a[1]), "r"(a[2]), "r"(a[3]), "r"(b0), "r"(b1));
}
// fp16 pack/split
__device__ __forceinline__ u32 hfpack(float upper, float lower) {
    u32 r; asm("cvt.rn.f16x2.f32 %0, %1, %2;" : "=r"(r) : "f"(upper), "f"(lower));
    return r;
}
__device__ __forceinline__ void hfsplit(float x0, float x1, u32& h, u32& l) {
    h = hfpack(x1, x0);
    __half2 hv = *reinterpret_cast<__half2*>(&h);
    float f0 = __low2float(hv);
    float f1 = __high2float(hv);
    l = hfpack(x1 - f1, x0 - f0);
}
__device__ __forceinline__ void mma_fp16(float* c, const u32* a, u32 b0, u32 b1) {
    asm volatile(
        "mma.sync.aligned.m16n8k16.row.col.f32.f16.f16.f32 "
        "{%0,%1,%2,%3}, {%4,%5,%6,%7}, {%8,%9}, {%0,%1,%2,%3};"
        : "+f"(c[0]), "+f"(c[1]), "+f"(c[2]), "+f"(c[3])
        : "r"(a[0]), "r"(a[1]), "r"(a[2]), "r"(a[3]), "r"(b0), "r"(b1));
}

// ---------------- stage 1: layernorm stats only ----------------
__global__ void ln_stats(const float* __restrict__ tok) {
    int t = blockIdx.x * 8 + (threadIdx.x >> 5);
    int lane = threadIdx.x & 31;
    const float4* src = (const float4*)(tok + (size_t)t * DD);
    float4 x = src[lane];
    float s  = x.x + x.y + x.z + x.w;
    float sq = x.x*x.x + x.y*x.y + x.z*x.z + x.w*x.w;
    s  = warpsum(s);
    sq = warpsum(sq);
    float mu  = s * (1.0f/128.0f);
    float var = sq * (1.0f/128.0f) - mu*mu;
    if (lane == 0) {
        g_mu[t] = mu;
        g_rs[t] = rsqrtf(var + LN_EPS);
    }
}

// ---------------- stage 2: QKV gemm, fp16 2-term (A-hi x (B-hi + B-lo)) ----------------
// Output quantized to fp16 anyway -> 2-mma accuracy suffices.
#define QKV_STAGE_U32 (64*20 + 16*136*2)            // 5632
#define QKV_SMEM (QKV_STAGE_U32 * 4 * 2)            // 45056 B

__global__ void __launch_bounds__(256, 2)
gemm_qkv(const float* __restrict__ tok,
         const float* __restrict__ lnw, const float* __restrict__ lnb,
         const float* __restrict__ wq,
         const float* __restrict__ wk,
         const float* __restrict__ wv) {
    constexpr int LDA_G = 128, LDB_G = 256, NCHUNK = 4;
    int m0 = blockIdx.x * 64;
    int n0 = blockIdx.y * 128;
    const float* Bg; int nb;
    if (n0 < 256)      { Bg = wq; nb = n0; }
    else if (n0 < 512) { Bg = wk; nb = n0 - 256; }
    else               { Bg = wv; nb = n0 - 512; }
    Bg += nb;
    const float* Ag = tok + (size_t)m0*128;
    __half* Cg = g_y + (size_t)m0*768 + n0;

    extern __shared__ __align__(16) u32 sq32[];
    u32* sbase = sq32;

    int tid = threadIdx.x;
    int lane = tid & 31, wid = tid >> 5;
    int g = lane >> 2, t = lane & 3;
    int warp_m = (wid >> 2) * 32;
    int warp_n = (wid & 3) * 32;

    float acc[2][4][4];
    #pragma unroll
    for (int i = 0; i < 2; i++)
        #pragma unroll
        for (int j = 0; j < 4; j++)
            #pragma unroll
            for (int r = 0; r < 4; r++) acc[i][j][r] = 0.0f;

    int a_row = tid >> 2;
    int a_c0  = (tid & 3) * 8;
    int b_kp  = tid >> 4;
    int b_n0  = (tid & 15) * 8;

    float a_mu = g_mu[m0 + a_row];
    float a_rs = g_rs[m0 + a_row];

    float4 aReg[2];
    float4 bReg[4];

    auto loadG = [&](int k0) {
        #pragma unroll
        for (int i = 0; i < 2; i++)
            aReg[i] = *(const float4*)&Ag[(size_t)a_row*LDA_G + k0 + a_c0 + i*4];
        const float* B0 = &Bg[(size_t)(k0 + 2*b_kp)*LDB_G + b_n0];
        bReg[0] = *(const float4*)B0;
        bReg[1] = *(const float4*)(B0 + 4);
        bReg[2] = *(const float4*)(B0 + LDB_G);
        bReg[3] = *(const float4*)(B0 + LDB_G + 4);
    };
    auto cvtStore = [&](int s, int k0) {
        u32* AsH = sbase + s*QKV_STAGE_U32;
        u32* BsH = AsH + 64*20;
        u32* BsL = BsH + 16*136;
        #pragma unroll
        for (int i = 0; i < 2; i++) {
            int c = a_c0 + i*4;
            float4 a4 = aReg[i];
            float4 w4 = *(const float4*)&lnw[k0 + c];
            float4 b4 = *(const float4*)&lnb[k0 + c];
            a4.x = (a4.x - a_mu) * a_rs * w4.x + b4.x;
            a4.y = (a4.y - a_mu) * a_rs * w4.y + b4.y;
            a4.z = (a4.z - a_mu) * a_rs * w4.z + b4.z;
            a4.w = (a4.w - a_mu) * a_rs * w4.w + b4.w;
            u32 h01 = hfpack(a4.y, a4.x);
            u32 h23 = hfpack(a4.w, a4.z);
            *(uint2*)&AsH[a_row*20 + (c >> 1)] = make_uint2(h01, h23);
        }
        u32 h[8], l[8];
        hfsplit(bReg[0].x, bReg[2].x, h[0], l[0]);
        hfsplit(bReg[0].y, bReg[2].y, h[1], l[1]);
        hfsplit(bReg[0].z, bReg[2].z, h[2], l[2]);
        hfsplit(bReg[0].w, bReg[2].w, h[3], l[3]);
        hfsplit(bReg[1].x, bReg[3].x, h[4], l[4]);
        hfsplit(bReg[1].y, bReg[3].y, h[5], l[5]);
        hfsplit(bReg[1].z, bReg[3].z, h[6], l[6]);
        hfsplit(bReg[1].w, bReg[3].w, h[7], l[7]);
        u32* dh = &BsH[b_kp*136 + b_n0];
        u32* dl = &BsL[b_kp*136 + b_n0];
        *(uint4*)dh       = make_uint4(h[0], h[1], h[2], h[3]);
        *(uint4*)(dh + 4) = make_uint4(h[4], h[5], h[6], h[7]);
        *(uint4*)dl       = make_uint4(l[0], l[1], l[2], l[3]);
        *(uint4*)(dl + 4) = make_uint4(l[4], l[5], l[6], l[7]);
    };

    loadG(0);
    cvtStore(0, 0);
    __syncthreads();

    for (int c = 0; c < NCHUNK; c++) {
        if (c + 1 < NCHUNK) loadG((c+1)*32);
        u32* AsH = sbase + (c & 1)*QKV_STAGE_U32;
        u32* BsH = AsH + 64*20;
        u32* BsL = BsH + 16*136;
        #pragma unroll
        for (int kk = 0; kk < 2; kk++) {
            int kp = kk*8;
            u32 bh[4][2], bl[4][2];
            #pragma unroll
            for (int nt = 0; nt < 4; nt++) {
                int n = warp_n + nt*8 + g;
                bh[nt][0] = BsH[(kp + t)*136 + n];
                bh[nt][1] = BsH[(kp + t + 4)*136 + n];
                bl[nt][0] = BsL[(kp + t)*136 + n];
                bl[nt][1] = BsL[(kp + t + 4)*136 + n];
            }
            #pragma unroll
            for (int mt = 0; mt < 2; mt++) {
                int m = warp_m + mt*16;
                u32 ah[4];
                ah[0] = AsH[(m + g)*20 + kp + t];
                ah[1] = AsH[(m + g + 8)*20 + kp + t];
                ah[2] = AsH[(m + g)*20 + kp + t + 4];
                ah[3] = AsH[(m + g + 8)*20 + kp + t + 4];
                #pragma unroll
                for (int nt = 0; nt < 4; nt++) {
                    mma_fp16(acc[mt][nt], ah, bh[nt][0], bh[nt][1]);
                    mma_fp16(acc[mt][nt], ah, bl[nt][0], bl[nt][1]);
                }
            }
        }
        if (c + 1 < NCHUNK) cvtStore((c+1) & 1, (c+1)*32);
        __syncthreads();
    }

    #pragma unroll
    for (int mt = 0; mt < 2; mt++) {
        #pragma unroll
        for (int nt = 0; nt < 4; nt++) {
            int r0 = warp_m + mt*16 + g;
            int col = warp_n + nt*8 + 2*t;
            *(u32*)&Cg[(size_t)r0*768 + col]       = hfpack(acc[mt][nt][1], acc[mt][nt][0]);
            *(u32*)&Cg[(size_t)(r0 + 8)*768 + col] = hfpack(acc[mt][nt][3], acc[mt][nt][2]);
        }
    }
}

// ---------------- stage 4: output gemm, 3xBF16 (accuracy-critical) ----------------
#define OUT_STAGE_U32 (64*40 + 16*136*2)
#define OUT_SMEM (OUT_STAGE_U32 * 4 * 2)

__global__ void __launch_bounds__(256, 2)
gemm_out(const float* __restrict__ wo,
         const float* __restrict__ tok,
         float* __restrict__ out) {
    constexpr int LDA_G = 256, LDB_G = 128, NCHUNK = 8;
    int m0 = blockIdx.x * 64;
    const float* Ag = g_ho + (size_t)m0*256;
    const float* Bg = wo;
    float* Cg = out + (size_t)m0*128;
    const float* Rg = tok + (size_t)m0*128;

    extern __shared__ __align__(16) u32 so32[];
    u32* sbase = so32;

    int tid = threadIdx.x;
    int lane = tid & 31, wid = tid >> 5;
    int g = lane >> 2, t = lane & 3;
    int warp_m = (wid >> 2) * 32;
    int warp_n = (wid & 3) * 32;

    float acc[2][4][4];
    #pragma unroll
    for (int i = 0; i < 2; i++)
        #pragma unroll
        for (int j = 0; j < 4; j++)
            #pragma unroll
            for (int r = 0; r < 4; r++) acc[i][j][r] = 0.0f;

    int a_row = tid >> 2;
    int a_c0  = (tid & 3) * 8;
    int b_kp  = tid >> 4;
    int b_n0  = (tid & 15) * 8;

    float4 aReg[2];
    float4 bReg[4];

    auto loadG = [&](int k0) {
        #pragma unroll
        for (int i = 0; i < 2; i++)
            aReg[i] = *(const float4*)&Ag[(size_t)a_row*LDA_G + k0 + a_c0 + i*4];
        const float* B0 = &Bg[(size_t)(k0 + 2*b_kp)*LDB_G + b_n0];
        bReg[0] = *(const float4*)B0;
        bReg[1] = *(const float4*)(B0 + 4);
        bReg[2] = *(const float4*)(B0 + LDB_G);
        bReg[3] = *(const float4*)(B0 + LDB_G + 4);
    };
    auto cvtStore = [&](int s) {
        u32* AsH = sbase + s*OUT_STAGE_U32;
        u32* AsL = AsH + 64*20;
        u32* BsH = AsL + 64*20;
        u32* BsL = BsH + 16*136;
        #pragma unroll
        for (int i = 0; i < 2; i++) {
            int c = a_c0 + i*4;
            float4 a4 = aReg[i];
            u32 h01, l01, h23, l23;
            bfsplit(a4.x, a4.y, h01, l01);
            bfsplit(a4.z, a4.w, h23, l23);
            int cu = c >> 1;
            *(uint2*)&AsH[a_row*20 + cu] = make_uint2(h01, h23);
            *(uint2*)&AsL[a_row*20 + cu] = make_uint2(l01, l23);
        }
        u32 h[8], l[8];
        bfsplit(bReg[0].x, bReg[2].x, h[0], l[0]);
        bfsplit(bReg[0].y, bReg[2].y, h[1], l[1]);
        bfsplit(bReg[0].z, bReg[2].z, h[2], l[2]);
        bfsplit(bReg[0].w, bReg[2].w, h[3], l[3]);
        bfsplit(bReg[1].x, bReg[3].x, h[4], l[4]);
        bfsplit(bReg[1].y, bReg[3].y, h[5], l[5]);
        bfsplit(bReg[1].z, bReg[3].z, h[6], l[6]);
        bfsplit(bReg[1].w, bReg[3].w, h[7], l[7]);
        u32* dh = &BsH[b_kp*136 + b_n0];
        u32* dl = &BsL[b_kp*136 + b_n0];
        *(uint4*)dh       = make_uint4(h[0], h[1], h[2], h[3]);
        *(uint4*)(dh + 4) = make_uint4(h[4], h[5], h[6], h[7]);
        *(uint4*)dl       = make_uint4(l[0], l[1], l[2], l[3]);
        *(uint4*)(dl + 4) = make_uint4(l[4], l[5], l[6], l[7]);
    };

    loadG(0);
    cvtStore(0);
    __syncthreads();

    for (int c = 0; c < NCHUNK; c++) {
        if (c + 1 < NCHUNK) loadG((c+1)*32);
        u32* AsH = sbase + (c & 1)*OUT_STAGE_U32;
        u32* AsL = AsH + 64*20;
        u32* BsH = AsL + 64*20;
        u32* BsL = BsH + 16*136;
        #pragma unroll
        for (int kk = 0; kk < 2; kk++) {
            int kp = kk*8;
            u32 bh[4][2], bl[4][2];
            #pragma unroll
            for (int nt = 0; nt < 4; nt++) {
                int n = warp_n + nt*8 + g;
                bh[nt][0] = BsH[(kp + t)*136 + n];
                bh[nt][1] = BsH[(kp + t + 4)*136 + n];
                bl[nt][0] = BsL[(kp + t)*136 + n];
                bl[nt][1] = BsL[(kp + t + 4)*136 + n];
            }
            #pragma unroll
            for (int mt = 0; mt < 2; mt++) {
                int m = warp_m + mt*16;
                u32 ah[4], al[4];
                ah[0] = AsH[(m + g)*20 + kp + t];
                ah[1] = AsH[(m + g + 8)*20 + kp + t];
                ah[2] = AsH[(m + g)*20 + kp + t + 4];
                ah[3] = AsH[(m + g + 8)*20 + kp + t + 4];
                al[0] = AsL[(m + g)*20 + kp + t];
                al[1] = AsL[(m + g + 8)*20 + kp + t];
                al[2] = AsL[(m + g)*20 + kp + t + 4];
                al[3] = AsL[(m + g + 8)*20 + kp + t + 4];
                #pragma unroll
                for (int nt = 0; nt < 4; nt++) {
                    mma_bf16(acc[mt][nt], ah, bh[nt][0], bh[nt][1]);
                    mma_bf16(acc[mt][nt], ah, bl[nt][0], bl[nt][1]);
                    mma_bf16(acc[mt][nt], al, bh[nt][0], bh[nt][1]);
                }
            }
        }
        if (c + 1 < NCHUNK) cvtStore((c+1) & 1);
        __syncthreads();
    }

    #pragma unroll
    for (int mt = 0; mt < 2; mt++) {
        #pragma unroll
        for (int nt = 0; nt < 4; nt++) {
            int r0 = warp_m + mt*16 + g;
            int col = warp_n + nt*8 + 2*t;
            float* d0 = Cg + (size_t)r0*128 + col;
            float* d1 = d0 + 8*128;
            const float* s0 = Rg + (size_t)r0*128 + col;
            const float* s1 = s0 + 8*128;
            float2 t0 = *(const float2*)s0;
            float2 t1 = *(const float2*)s1;
            *(float2*)d0 = make_float2(acc[mt][nt][0] + t0.x, acc[mt][nt][1] + t0.y);
            *(float2*)d1 = make_float2(acc[mt][nt][2] + t1.x, acc[mt][nt][3] + t1.y);
        }
    }
}

// ---------------- stage 3: fp16 TC banded differential attention ----------------
// g_y already fp16: loaders are copies. Q 1-term, K 1-term (1-mma scores),
// P 2-term, V 1-term (2-mma PV). smem 75 KB, 2 CTAs/SM.
#define ATTN_SMEM ((KRP*KPL + 64*VLD) * 4)

__global__ void __launch_bounds__(256, 2)
attn_kernel(const float* __restrict__ lq1, const float* __restrict__ lk1,
            const float* __restrict__ lq2, const float* __restrict__ lk2,
            const float* __restrict__ sigS, const float* __restrict__ sigN,
            const float* __restrict__ hnw,  const float* __restrict__ hnb) {
    extern __shared__ __align__(16) u32 smu[];
    u32* Kh = smu;                  // [KRP][KPL] fp16x2 (d, d+1)
    u32* Vh = Kh + KRP*KPL;         // [64][VLD] d-major, fp16x2 (j, j+1)
    __shared__ float s_lam;

    int tid = threadIdx.x;
    int bh  = blockIdx.y;
    int b   = bh >> 2;
    int h   = bh & 3;
    int q0  = blockIdx.x * QTA;

    float ss = fmaxf(sigS[0], 1.0f), sn = fmaxf(sigN[0], 1.0f);
    float c1 = -0.5f / (ss*ss);
    float c2 = -0.5f / (sn*sn);
    int Wn = (int)ceilf(6.0f * fmaxf(ss, sn)); if (Wn > W_MAX) Wn = W_MAX;
    int W1 = (int)ceilf(6.0f * ss);            if (W1 > W_MAX) W1 = W_MAX;

    int blo = q0 - Wn;            if (blo < 0) blo = 0;
    int bhi = q0 + QTA - 1 + Wn;  if (bhi > TT-1) bhi = TT-1;
    int nrows = bhi - blo + 1;

    const __half* ybase = g_y + (size_t)(b*TT) * 768;

    // --- K band copy (u32 = fp16 pair along d), zero-fill padding ---
    for (int idx = tid; idx < KRP*32; idx += 256) {
        int r = idx >> 5, gi = idx & 31;
        u32 v = 0;
        if (r < nrows)
            v = ((const u32*)(ybase + (size_t)(blo + r)*768 + h*64 + 256))[gi];
        Kh[r*KPL + gi] = v;
    }
    // --- V transpose: (j,j+1) pairs per d via byte_perm ---
    for (int idx = tid; idx < JPFILL*32; idx += 256) {
        int jp = idx >> 5, dg = idx & 31;
        int r0 = 2*jp, r1 = 2*jp + 1;
        u32 a = 0, bb = 0;
        if (r0 < nrows) a  = ((const u32*)(ybase + (size_t)(blo + r0)*768 + h*64 + 512))[dg];
        if (r1 < nrows) bb = ((const u32*)(ybase + (size_t)(blo + r1)*768 + h*64 + 512))[dg];
        Vh[(2*dg)*VLD + jp]     = __byte_perm(a, bb, 0x5410);
        Vh[(2*dg + 1)*VLD + jp] = __byte_perm(a, bb, 0x7632);
    }
    if (tid == 0) {
        float d1 = 0.0f, d2 = 0.0f;
        #pragma unroll
        for (int i = 0; i < 32; i++) { d1 += lq1[i]*lk1[i]; d2 += lq2[i]*lk2[i]; }
        s_lam = __expf(d1) - __expf(d2) + LAMBDA_INIT;
    }
    __syncthreads();
    float lam = s_lam;

    int w = tid >> 5, lane = tid & 31;
    int g = lane >> 2, t = lane & 3;
    int i0 = q0 + w*16;

    // --- Q A-frags: direct u32 loads (fp16 pairs) ---
    u32 Qf[2][2][4];
    {
        const __half* qr0 = ybase + (size_t)(i0 + g)*768 + h*64;
        const __half* qr1 = qr0 + (size_t)8*768;
        #pragma unroll
        for (int m = 0; m < 2; m++) {
            #pragma unroll
            for (int s = 0; s < 2; s++) {
                int d0 = m*32 + s*16 + 2*t;
                Qf[m][s][0] = *(const u32*)(qr0 + d0);
                Qf[m][s][1] = *(const u32*)(qr1 + d0);
                Qf[m][s][2] = *(const u32*)(qr0 + d0 + 8);
                Qf[m][s][3] = *(const u32*)(qr1 + d0 + 8);
            }
        }
    }

    float o2[8][4], o1[8][4];
    #pragma unroll
    for (int nt = 0; nt < 8; nt++)
        #pragma unroll
        for (int r = 0; r < 4; r++) { o2[nt][r] = 0.0f; o1[nt][r] = 0.0f; }
    float l2p0 = 0.0f, l2p1 = 0.0f, l1p0 = 0.0f, l1p1 = 0.0f;

    int i0rel = i0 - blo;
    int jloW = i0 - Wn;           if (jloW < blo) jloW = blo;
    int jhiW = i0 + 15 + Wn;      if (jhiW > bhi) jhiW = bhi;
    int jsrel0 = (jloW - blo) & ~1;
    int jendrel = jhiW - blo;
    int m1loR = i0rel - W1, m1hiR = i0rel + 15 + W1;

    for (int js = jsrel0; js <= jendrel; js += 16) {
        float e2[2][4], e1[2][4];
        bool act1[2];
        #pragma unroll
        for (int e = 0; e < 2; e++) {
            int jb = js + 8*e;
            const u32* kr = Kh + (jb + g)*KPL;
            float c[4] = {0.0f, 0.0f, 0.0f, 0.0f};
            #pragma unroll
            for (int s = 0; s < 2; s++) {
                int kp = 16 + 8*s + t;
                mma_fp16(c, Qf[1][s], kr[kp], kr[kp + 4]);
            }
            int jc0 = jb + 2*t;
            bool v0 = jc0 < nrows, v1 = (jc0 + 1) < nrows;
            float r0 = (float)(jc0 + blo - i0 - g);
            float r1 = r0 + 1.0f;
            float r2 = r0 - 8.0f;
            float r3 = r2 + 1.0f;
            e2[e][0] = v0 ? __expf(c[0]*SCALE + r0*r0*c2) : 0.0f;
            e2[e][1] = v1 ? __expf(c[1]*SCALE + r1*r1*c2) : 0.0f;
            e2[e][2] = v0 ? __expf(c[2]*SCALE + r2*r2*c2) : 0.0f;
            e2[e][3] = v1 ? __expf(c[3]*SCALE + r3*r3*c2) : 0.0f;
            l2p0 += e2[e][0] + e2[e][1];
            l2p1 += e2[e][2] + e2[e][3];
            act1[e] = (jb <= m1hiR) && (jb + 7 >= m1loR);
            if (act1[e]) {
                float d[4] = {0.0f, 0.0f, 0.0f, 0.0f};
                #pragma unroll
                for (int s = 0; s < 2; s++) {
                    int kp = 8*s + t;
                    mma_fp16(d, Qf[0][s], kr[kp], kr[kp + 4]);
                }
                e1[e][0] = v0 ? __expf(d[0]*SCALE + r0*r0*c1) : 0.0f;
                e1[e][1] = v1 ? __expf(d[1]*SCALE + r1*r1*c1) : 0.0f;
                e1[e][2] = v0 ? __expf(d[2]*SCALE + r2*r2*c1) : 0.0f;
                e1[e][3] = v1 ? __expf(d[3]*SCALE + r3*r3*c1) : 0.0f;
                l1p0 += e1[e][0] + e1[e][1];
                l1p1 += e1[e][2] + e1[e][3];
            } else {
                e1[e][0] = e1[e][1] = e1[e][2] = e1[e][3] = 0.0f;
            }
        }
        // C->A repack (2-term fp16 P)
        u32 p2h[4], p2l[4], p1h[4], p1l[4];
        hfsplit(e2[0][0], e2[0][1], p2h[0], p2l[0]);
        hfsplit(e2[0][2], e2[0][3], p2h[1], p2l[1]);
        hfsplit(e2[1][0], e2[1][1], p2h[2], p2l[2]);
        hfsplit(e2[1][2], e2[1][3], p2h[3], p2l[3]);
        bool anyM1 = act1[0] || act1[1];
        if (anyM1) {
            hfsplit(e1[0][0], e1[0][1], p1h[0], p1l[0]);
            hfsplit(e1[0][2], e1[0][3], p1h[1], p1l[1]);
            hfsplit(e1[1][0], e1[1][1], p1h[2], p1l[2]);
            hfsplit(e1[1][2], e1[1][3], p1h[3], p1l[3]);
        }
        // PV: 2-term P x 1-term V
        int jpb = js >> 1;
        #pragma unroll
        for (int nt = 0; nt < 8; nt++) {
            const u32* vh = Vh + (nt*8 + g)*VLD + jpb;
            u32 bh0 = vh[t], bh1 = vh[t + 4];
            mma_fp16(o2[nt], p2h, bh0, bh1);
            mma_fp16(o2[nt], p2l, bh0, bh1);
            if (anyM1) {
                mma_fp16(o1[nt], p1h, bh0, bh1);
                mma_fp16(o1[nt], p1l, bh0, bh1);
            }
        }
    }

    // --- epilogue: normalize, combine, per-head LN(64), scale, store ---
    float L2a = quadsum(l2p0), L2b = quadsum(l2p1);
    float L1a = quadsum(l1p0), L1b = quadsum(l1p1);
    float il1a = 1.0f / L1a, il1b = 1.0f / L1b;
    float il2a = lam / L2a,  il2b = lam / L2b;

    float val[8][4];
    float sA = 0, qA = 0, sB = 0, qB = 0;
    #pragma unroll
    for (int nt = 0; nt < 8; nt++) {
        float v0 = o1[nt][0]*il1a - o2[nt][0]*il2a;
        float v1 = o1[nt][1]*il1a - o2[nt][1]*il2a;
        float v2 = o1[nt][2]*il1b - o2[nt][2]*il2b;
        float v3 = o1[nt][3]*il1b - o2[nt][3]*il2b;
        val[nt][0] = v0; val[nt][1] = v1; val[nt][2] = v2; val[nt][3] = v3;
        sA += v0 + v1;  qA += v0*v0 + v1*v1;
        sB += v2 + v3;  qB += v2*v2 + v3*v3;
    }
    sA = quadsum(sA); qA = quadsum(qA);
    sB = quadsum(sB); qB = quadsum(qB);
    float muA = sA * (1.0f/64.0f);
    float rsA = rsqrtf(qA * (1.0f/64.0f) - muA*muA + LN_EPS);
    float muB = sB * (1.0f/64.0f);
    float rsB = rsqrtf(qB * (1.0f/64.0f) - muB*muB + LN_EPS);
    float post = 1.0f - LAMBDA_INIT;

    float* dstA = g_ho + (size_t)(b*TT + i0 + g)*256 + h*64;
    float* dstB = dstA + (size_t)8*256;
    #pragma unroll
    for (int nt = 0; nt < 8; nt++) {
        int d0 = nt*8 + 2*t;
        float2 w2 = *(const float2*)&hnw[d0];
        float2 b2 = *(const float2*)&hnb[d0];
        float y0 = ((val[nt][0] - muA)*rsA*w2.x + b2.x) * post;
        float y1 = ((val[nt][1] - muA)*rsA*w2.y + b2.y) * post;
        float y2 = ((val[nt][2] - muB)*rsB*w2.x + b2.x) * post;
        float y3 = ((val[nt][3] - muB)*rsB*w2.y + b2.y) * post;
        *(float2*)(dstA + d0) = make_float2(y0, y1);
        *(float2*)(dstB + d0) = make_float2(y2, y3);
    }
}

// ---------------- launch ----------------
extern "C" void kernel_launch(void* const* d_in, const int* in_sizes, int n_in,
                              void* d_out, int out_size) {
    const float* tokens = (const float*)d_in[0];
    const float* ln_w   = (const float*)d_in[1];
    const float* ln_b   = (const float*)d_in[2];
    const float* wq     = (const float*)d_in[3];
    const float* wk     = (const float*)d_in[4];
    const float* wv     = (const float*)d_in[5];
    const float* wo     = (const float*)d_in[6];
    const float* lq1    = (const float*)d_in[7];
    const float* lk1    = (const float*)d_in[8];
    const float* lq2    = (const float*)d_in[9];
    const float* lk2    = (const float*)d_in[10];
    const float* sigS   = (const float*)d_in[11];
    const float* sigN   = (const float*)d_in[12];
    const float* hnw    = (const float*)d_in[13];
    const float* hnb    = (const float*)d_in[14];
    float* out = (float*)d_out;

    cudaFuncSetAttribute(attn_kernel, cudaFuncAttributeMaxDynamicSharedMemorySize, ATTN_SMEM);
    cudaFuncSetAttribute(gemm_qkv, cudaFuncAttributeMaxDynamicSharedMemorySize, QKV_SMEM);
    cudaFuncSetAttribute(gemm_out, cudaFuncAttributeMaxDynamicSharedMemorySize, OUT_SMEM);

    ln_stats<<<NTOK/8, 256>>>(tokens);
    gemm_qkv<<<dim3(NTOK/64, 6), 256, QKV_SMEM>>>(tokens, ln_w, ln_b, wq, wk, wv);
    attn_kernel<<<dim3(TT/QTA, BB*HH), 256, ATTN_SMEM>>>(lq1, lk1, lq2, lk2, sigS, sigN, hnw, hnb);
    gemm_out<<<NTOK/64, 256, OUT_SMEM>>>(wo, tokens, out);
}